// round 4
// baseline (speedup 1.0000x reference)
#include <cuda_runtime.h>
#include <math.h>

// ---------------- problem constants ----------------
#define NB    4          // batch
#define NC    32         // channels
#define NSP   1024       // spatial N = H*W
#define ND    1024       // per-head feature dim d
#define NBH   16         // B*HEADS
#define NHID  4096       // hidden
#define SCALE 0.17677669529663687f   // 1/sqrt(32)
#define EPSGN 1e-5f

// ---------------- scratch (device globals; allocation-free) ----------------
__device__ float g_Q  [NBH * ND * NSP];   // q natural [bh][d][n]
__device__ float g_K  [NBH * ND * NSP];   // k natural [bh][d][n]
__device__ float g_V  [NBH * ND * NSP];   // v natural [bh][e][n]
__device__ float g_KT [NBH * NSP * ND];   // k softmaxed, transposed [bh][n][d]
__device__ float g_VT [NBH * NSP * ND];   // v transposed [bh][n][e]
__device__ float g_CTX[NBH * ND * ND];    // context [bh][d][e]
__device__ float g_X  [NBH * ND * NSP];   // attention out [bh][e][n] == [b][(h,e)][n]
__device__ float g_Y  [NB * NC * NSP];    // projection out, pre-GN
__device__ float g_stats[8];              // mean[4], var[4]

// packed dual-fp32 FMA (Blackwell f32x2 pipe)
#define FMA2(c, a, b) asm("fma.rn.f32x2 %0, %1, %2, %0;" : "+l"(c) : "l"(a), "l"(b))

// ============================================================
// Kernel 1: QKV projection. out[o,n] = sum_c img[c,n]*w[o,c] + bias[o]
// scatter into q/k/v natural layouts.
// block: 256 thr; tile o=64, n=128; micro 8o x 4n per thread.
// grid: (8 n-tiles, 192 o-tiles, 4 b)
// ============================================================
__global__ __launch_bounds__(256) void qkv_kernel(const float* __restrict__ img,
                                                  const float* __restrict__ w,
                                                  const float* __restrict__ bias) {
    __shared__ float xs[32][128];
    __shared__ float ws[64][32];
    __shared__ float bs[64];

    const int b  = blockIdx.z;
    const int o0 = blockIdx.y * 64;
    const int n0 = blockIdx.x * 128;
    const int t  = threadIdx.x;

    // load image tile 32c x 128n (1024 float4)
#pragma unroll
    for (int i = 0; i < 4; i++) {
        int idx = t + 256 * i;            // float4 index
        int c = idx >> 5, c4 = (idx & 31) << 2;
        *(float4*)&xs[c][c4] =
            *(const float4*)&img[((size_t)b * 32 + c) * 1024 + n0 + c4];
    }
    // load weight tile 64o x 32c (512 float4)
#pragma unroll
    for (int i = 0; i < 2; i++) {
        int idx = t + 256 * i;
        int o = idx >> 3, c4 = (idx & 7) << 2;
        *(float4*)&ws[o][c4] = *(const float4*)&w[(size_t)(o0 + o) * 32 + c4];
    }
    if (t < 64) bs[t] = bias[o0 + t];
    __syncthreads();

    const int tx = t & 31;   // n-group: n = n0 + 4*tx
    const int oy = t >> 5;   // o-group: o = o0 + 8*oy + r

    float acc[8][4];
#pragma unroll
    for (int r = 0; r < 8; r++) {
        float bv = bs[8 * oy + r];
#pragma unroll
        for (int i = 0; i < 4; i++) acc[r][i] = bv;
    }

#pragma unroll
    for (int c = 0; c < 32; c++) {
        float4 x = *(const float4*)&xs[c][4 * tx];
#pragma unroll
        for (int r = 0; r < 8; r++) {
            float wv = ws[8 * oy + r][c];
            acc[r][0] += wv * x.x;
            acc[r][1] += wv * x.y;
            acc[r][2] += wv * x.z;
            acc[r][3] += wv * x.w;
        }
    }

    const int nglob = n0 + 4 * tx;
#pragma unroll
    for (int r = 0; r < 8; r++) {
        int o     = o0 + 8 * oy + r;
        int which = o >> 12;          // 0=q 1=k 2=v
        int oc    = o & 4095;
        int h     = oc & 3;           // channel = c*HEADS + h
        int cch   = oc >> 2;
        float* dst = (which == 0) ? g_Q : (which == 1) ? g_K : g_V;
        float4 st = make_float4(acc[r][0], acc[r][1], acc[r][2], acc[r][3]);
        *(float4*)&dst[(((size_t)b * 4 + h) << 20) + (size_t)cch * 1024 + nglob] = st;
    }
}

// ============================================================
// Kernel 2: q softmax over d (columns of [d,n]), in place, *SCALE.
// block 512 thr (16 warps); warp w covers d in [w*64,w*64+64), lane = column.
// grid: (32 n-tiles, 16 bh)
// ============================================================
__global__ __launch_bounds__(512) void q_softmax_kernel() {
    const int z    = blockIdx.y;
    const int lane = threadIdx.x & 31;
    const int w    = threadIdx.x >> 5;
    float* base = g_Q + ((size_t)z << 20) + blockIdx.x * 32 + lane;

    float vals[64];
    float lmax = -3.402823466e38f;
#pragma unroll
    for (int i = 0; i < 64; i++) {
        vals[i] = base[(size_t)(w * 64 + i) * 1024];
        lmax = fmaxf(lmax, vals[i]);
    }
    __shared__ float red[16][32];
    red[w][lane] = lmax;
    __syncthreads();
    float cmax = red[0][lane];
#pragma unroll
    for (int r = 1; r < 16; r++) cmax = fmaxf(cmax, red[r][lane]);

    float lsum = 0.f;
#pragma unroll
    for (int i = 0; i < 64; i++) {
        vals[i] = expf(vals[i] - cmax);
        lsum += vals[i];
    }
    __syncthreads();
    red[w][lane] = lsum;
    __syncthreads();
    float csum = 0.f;
#pragma unroll
    for (int r = 0; r < 16; r++) csum += red[r][lane];

    float rs = SCALE / csum;
#pragma unroll
    for (int i = 0; i < 64; i++) base[(size_t)(w * 64 + i) * 1024] = vals[i] * rs;
}

// ============================================================
// Kernel 3: k softmax over n (rows) + transpose -> kT[n][d].
// block 1024 thr (32 warps); warp = one d-row; lane holds 32 n-values.
// grid: (32 d-tiles, 16 bh)
// ============================================================
__global__ __launch_bounds__(1024) void k_softmax_t_kernel() {
    const int z    = blockIdx.y;
    const int lane = threadIdx.x & 31;
    const int w    = threadIdx.x >> 5;
    const int d0   = blockIdx.x * 32;
    const float* src = g_K + ((size_t)z << 20) + (size_t)(d0 + w) * 1024;

    float vals[32];
    float m = -3.402823466e38f;
#pragma unroll
    for (int j = 0; j < 32; j++) {
        vals[j] = src[j * 32 + lane];
        m = fmaxf(m, vals[j]);
    }
#pragma unroll
    for (int o = 16; o; o >>= 1) m = fmaxf(m, __shfl_xor_sync(0xffffffffu, m, o));
    float s = 0.f;
#pragma unroll
    for (int j = 0; j < 32; j++) {
        vals[j] = expf(vals[j] - m);
        s += vals[j];
    }
#pragma unroll
    for (int o = 16; o; o >>= 1) s += __shfl_xor_sync(0xffffffffu, s, o);
    float inv = 1.f / s;
#pragma unroll
    for (int j = 0; j < 32; j++) vals[j] *= inv;

    __shared__ float sT[32][33];
    float* dstb = g_KT + ((size_t)z << 20);
#pragma unroll 1
    for (int j = 0; j < 32; j++) {           // n-tile j: n = 32*j + ...
        sT[lane][w] = vals[j];               // sT[n_local][d_local]
        __syncthreads();
        dstb[(size_t)(j * 32 + w) * 1024 + d0 + lane] = sT[w][lane];
        __syncthreads();
    }
}

// ============================================================
// Kernel 4: v transpose -> vT[n][e].  block (32,8), 32x32 tiles.
// grid: (32 n-tiles, 32 d-tiles, 16 bh)
// ============================================================
__global__ void v_transpose_kernel() {
    __shared__ float s[32][33];
    const int z  = blockIdx.z;
    const int d0 = blockIdx.y * 32;
    const int n0 = blockIdx.x * 32;
    const int tx = threadIdx.x, ty = threadIdx.y;
    const float* src = g_V + ((size_t)z << 20);
    float* dst = g_VT + ((size_t)z << 20);
#pragma unroll
    for (int i = 0; i < 4; i++)
        s[ty + 8 * i][tx] = src[(size_t)(d0 + ty + 8 * i) * 1024 + n0 + tx];
    __syncthreads();
#pragma unroll
    for (int i = 0; i < 4; i++)
        dst[(size_t)(n0 + ty + 8 * i) * 1024 + d0 + tx] = s[tx][ty + 8 * i];
}

// ============================================================
// Kernel 5: TN GEMM, C[m,n] = sum_k A[k,m]*B[k,n], 1024^3 per z.
// stage 0: A=kT, B=vT, C=ctx.   stage 1: A=ctx, B=q, C=X.
// 128x128 block tile, K-tile 16, 8x8 micro via packed f32x2 FMA.
// A-tile stored DUPLICATED in smem ([k][2m]) so the f32x2 'a' operand
// is a pre-paired (v,v) without per-iteration MOVs.
// grid (8,8,16), block 256.
// ============================================================
__global__ __launch_bounds__(256, 2) void tn_gemm_kernel(int stage) {
    const float* A = (stage == 0) ? g_KT  : g_CTX;
    const float* Bm = (stage == 0) ? g_VT : g_Q;
    float*       Cm = (stage == 0) ? g_CTX : g_X;
    const size_t zoff = (size_t)blockIdx.z << 20;
    A += zoff; Bm += zoff; Cm += zoff;

    const int m0 = blockIdx.y * 128;
    const int n0 = blockIdx.x * 128;

    __shared__ float Asd[16][256];   // duplicated: Asd[k][2m]=Asd[k][2m+1]=A[k][m]
    __shared__ float Bs[16][128];

    const int t   = threadIdx.x;
    const int tx  = t & 15, ty = t >> 4;
    const int lkr = t >> 5;              // 0..7 (k-row for loads)
    const int lc4 = (t & 31) * 4;        // 0..124 (col for loads)

    unsigned long long acc[8][4];
#pragma unroll
    for (int i = 0; i < 8; i++)
#pragma unroll
        for (int j = 0; j < 4; j++) acc[i][j] = 0ull;

    float4 pa0, pa1, pb0, pb1;
    {
        const float* Ap = A + (size_t)lkr * 1024 + m0 + lc4;
        pa0 = *(const float4*)Ap;
        pa1 = *(const float4*)(Ap + 8 * 1024);
        const float* Bp = Bm + (size_t)lkr * 1024 + n0 + lc4;
        pb0 = *(const float4*)Bp;
        pb1 = *(const float4*)(Bp + 8 * 1024);
    }

    for (int kt = 0; kt < 64; kt++) {
        __syncthreads();
        *(float4*)&Asd[lkr][2 * lc4]         = make_float4(pa0.x, pa0.x, pa0.y, pa0.y);
        *(float4*)&Asd[lkr][2 * lc4 + 4]     = make_float4(pa0.z, pa0.z, pa0.w, pa0.w);
        *(float4*)&Asd[lkr + 8][2 * lc4]     = make_float4(pa1.x, pa1.x, pa1.y, pa1.y);
        *(float4*)&Asd[lkr + 8][2 * lc4 + 4] = make_float4(pa1.z, pa1.z, pa1.w, pa1.w);
        *(float4*)&Bs[lkr][lc4]     = pb0;
        *(float4*)&Bs[lkr + 8][lc4] = pb1;
        __syncthreads();

        if (kt < 63) {
            const float* Ap = A + (size_t)((kt + 1) * 16 + lkr) * 1024 + m0 + lc4;
            pa0 = *(const float4*)Ap;
            pa1 = *(const float4*)(Ap + 8 * 1024);
            const float* Bp = Bm + (size_t)((kt + 1) * 16 + lkr) * 1024 + n0 + lc4;
            pb0 = *(const float4*)Bp;
            pb1 = *(const float4*)(Bp + 8 * 1024);
        }

#pragma unroll
        for (int kk = 0; kk < 16; kk++) {
            ulonglong2 aA = *(const ulonglong2*)&Asd[kk][8 * ty];
            ulonglong2 aB = *(const ulonglong2*)&Asd[kk][8 * ty + 4];
            ulonglong2 aC = *(const ulonglong2*)&Asd[kk][128 + 8 * ty];
            ulonglong2 aD = *(const ulonglong2*)&Asd[kk][128 + 8 * ty + 4];
            ulonglong2 b0 = *(const ulonglong2*)&Bs[kk][4 * tx];
            ulonglong2 b1 = *(const ulonglong2*)&Bs[kk][64 + 4 * tx];
            unsigned long long av[8] = {aA.x, aA.y, aB.x, aB.y, aC.x, aC.y, aD.x, aD.y};
            unsigned long long bv[4] = {b0.x, b0.y, b1.x, b1.y};
#pragma unroll
            for (int i = 0; i < 8; i++)
#pragma unroll
                for (int j = 0; j < 4; j++) FMA2(acc[i][j], av[i], bv[j]);
        }
    }

#pragma unroll
    for (int i = 0; i < 8; i++) {
        int m = m0 + ((i < 4) ? (4 * ty + i) : (64 + 4 * ty + (i - 4)));
        float* Cp = Cm + (size_t)m * 1024 + n0;
        ulonglong2 u0; u0.x = acc[i][0]; u0.y = acc[i][1];
        ulonglong2 u1; u1.x = acc[i][2]; u1.y = acc[i][3];
        *(ulonglong2*)(Cp + 4 * tx)      = u0;
        *(ulonglong2*)(Cp + 64 + 4 * tx) = u1;
    }
}

// ============================================================
// Kernel 6: output projection. Y[b,o,n] = b_out[o] + sum_c X[b,c,n]*w_out[o,c]
// block 256: 32 n-cols x 8 o-groups of 4. grid (32 n-tiles, 4 b).
// ============================================================
__global__ __launch_bounds__(256) void proj_kernel(const float* __restrict__ wout,
                                                   const float* __restrict__ bout) {
    __shared__ float ws[32][64];
    const int b  = blockIdx.y;
    const int n  = blockIdx.x * 32 + (threadIdx.x & 31);
    const int og = threadIdx.x >> 5;   // 0..7
    const float* X = g_X + ((size_t)b << 22);

    float acc[4];
#pragma unroll
    for (int j = 0; j < 4; j++) acc[j] = bout[og * 4 + j];

    for (int c0 = 0; c0 < 4096; c0 += 64) {
        __syncthreads();
#pragma unroll
        for (int i = 0; i < 2; i++) {
            int idx = threadIdx.x + 256 * i;       // float4 idx over 512
            int o = idx >> 4, c4 = (idx & 15) << 2;
            *(float4*)&ws[o][c4] = *(const float4*)&wout[(size_t)o * 4096 + c0 + c4];
        }
        __syncthreads();
#pragma unroll 16
        for (int cl = 0; cl < 64; cl++) {
            float x = X[(size_t)(c0 + cl) * 1024 + n];
#pragma unroll
            for (int j = 0; j < 4; j++) acc[j] += ws[og * 4 + j][cl] * x;
        }
    }
#pragma unroll
    for (int j = 0; j < 4; j++)
        g_Y[((size_t)b * 32 + og * 4 + j) * 1024 + n] = acc[j];
}

// ============================================================
// Kernel 7: per-batch mean/var (deterministic tree reduction).
// ============================================================
__global__ __launch_bounds__(1024) void stats_kernel() {
    __shared__ float ss[32], ss2[32];
    const int b = blockIdx.x, t = threadIdx.x;
    const float* Y = g_Y + (size_t)b * 32768;
    float s = 0.f, s2 = 0.f;
#pragma unroll
    for (int k = 0; k < 32; k++) {
        float v = Y[t + 1024 * k];
        s += v; s2 += v * v;
    }
#pragma unroll
    for (int o = 16; o; o >>= 1) {
        s  += __shfl_xor_sync(0xffffffffu, s, o);
        s2 += __shfl_xor_sync(0xffffffffu, s2, o);
    }
    if ((t & 31) == 0) { ss[t >> 5] = s; ss2[t >> 5] = s2; }
    __syncthreads();
    if (t < 32) {
        s = ss[t]; s2 = ss2[t];
#pragma unroll
        for (int o = 16; o; o >>= 1) {
            s  += __shfl_xor_sync(0xffffffffu, s, o);
            s2 += __shfl_xor_sync(0xffffffffu, s2, o);
        }
        if (t == 0) {
            float mean = s * (1.f / 32768.f);
            g_stats[b]     = mean;
            g_stats[4 + b] = s2 * (1.f / 32768.f) - mean * mean;
        }
    }
}

// ============================================================
// Kernel 8: GroupNorm finalize -> d_out.
// ============================================================
__global__ void gn_kernel(const float* __restrict__ gamma,
                          const float* __restrict__ beta,
                          float* __restrict__ out) {
    int idx = blockIdx.x * 256 + threadIdx.x;       // < 131072
    int b = idx >> 15;
    int o = (idx >> 10) & 31;
    float mean = g_stats[b];
    float rstd = rsqrtf(g_stats[4 + b] + EPSGN);
    out[idx] = (g_Y[idx] - mean) * rstd * gamma[o] + beta[o];
}

// ============================================================
extern "C" void kernel_launch(void* const* d_in, const int* in_sizes, int n_in,
                              void* d_out, int out_size) {
    (void)in_sizes; (void)n_in; (void)out_size;
    const float* image = (const float*)d_in[0];
    const float* w_qkv = (const float*)d_in[1];
    const float* b_qkv = (const float*)d_in[2];
    const float* w_out = (const float*)d_in[3];
    const float* b_out = (const float*)d_in[4];
    const float* gamma = (const float*)d_in[5];
    const float* beta  = (const float*)d_in[6];
    float* out = (float*)d_out;

    qkv_kernel<<<dim3(8, 192, 4), 256>>>(image, w_qkv, b_qkv);
    q_softmax_kernel<<<dim3(32, 16), 512>>>();
    k_softmax_t_kernel<<<dim3(32, 16), 1024>>>();
    v_transpose_kernel<<<dim3(32, 32, 16), dim3(32, 8)>>>();
    tn_gemm_kernel<<<dim3(8, 8, 16), 256>>>(0);   // context = kT^T * vT
    tn_gemm_kernel<<<dim3(8, 8, 16), 256>>>(1);   // X = ctx^T * q
    proj_kernel<<<dim3(32, 4), 256>>>(w_out, b_out);
    stats_kernel<<<4, 1024>>>();
    gn_kernel<<<512, 256>>>(gamma, beta, out);
}

// round 6
// speedup vs baseline: 1.6306x; 1.6306x over previous
#include <cuda_runtime.h>
#include <cuda_bf16.h>
#include <math.h>
#include <stdint.h>

// ---------------- problem constants ----------------
#define NB    4
#define NC    32
#define NSP   1024
#define ND    1024
#define NBH   16
#define SCALE 0.17677669529663687f   // 1/sqrt(32)
#define EPSGN 1e-5f

// ---------------- scratch (device globals; allocation-free) ----------------
__device__ float g_Q  [NBH * ND * NSP];       // q natural [bh][d][n] fp32 (pre-softmax)
__device__ float g_K  [NBH * ND * NSP];       // k natural [bh][d][n] fp32 (pre-softmax)
__device__ float g_X  [NBH * ND * NSP];       // attention out [bh][e][n] fp32
__device__ float g_Y  [NB * NC * NSP];        // projection out, pre-GN
__device__ float g_stats[8];                  // mean[4], var[4]
__device__ float g_qinv[NBH * NSP];           // SCALE / sum(exp(q)) per (z,n)

// bf16 hi/lo operand arrays (uint4-backed for 16B alignment)
#define BFN (NBH * ND * NSP / 8)
__device__ uint4 g_Vh4[BFN]; __device__ uint4 g_Vl4[BFN];   // v  [e][n]
__device__ uint4 g_Kh4[BFN]; __device__ uint4 g_Kl4[BFN];   // k softmaxed [d][n]
__device__ uint4 g_Qh4[BFN]; __device__ uint4 g_Ql4[BFN];   // qT softmaxed [n][d]
__device__ uint4 g_Ch4[BFN]; __device__ uint4 g_Cl4[BFN];   // ctx^T [e][d]

// ---------------- small helpers ----------------
__device__ __forceinline__ uint32_t smem_u32(const void* p) {
    uint32_t a;
    asm("{ .reg .u64 t; cvta.to.shared.u64 t, %1; cvt.u32.u64 %0, t; }" : "=r"(a) : "l"(p));
    return a;
}
__device__ __forceinline__ unsigned packbf(float a, float b) {
    __nv_bfloat162 p = __floats2bfloat162_rn(a, b);
    return *reinterpret_cast<unsigned*>(&p);
}
__device__ __forceinline__ void cpasync16(uint32_t saddr, const void* g) {
    asm volatile("cp.async.cg.shared.global [%0], [%1], 16;" :: "r"(saddr), "l"(g));
}
__device__ __forceinline__ void cp_commit() {
    asm volatile("cp.async.commit_group;" ::: "memory");
}
__device__ __forceinline__ void cp_wait1() {
    asm volatile("cp.async.wait_group 1;" ::: "memory");
}
__device__ __forceinline__ void cp_wait0() {
    asm volatile("cp.async.wait_group 0;" ::: "memory");
}
__device__ __forceinline__ void ldsm4(unsigned* r, uint32_t addr) {
    asm volatile("ldmatrix.sync.aligned.m8n8.x4.shared.b16 {%0,%1,%2,%3}, [%4];"
                 : "=r"(r[0]), "=r"(r[1]), "=r"(r[2]), "=r"(r[3]) : "r"(addr));
}
__device__ __forceinline__ void mma16816(float* c, const unsigned* a, const unsigned* b) {
    asm volatile(
        "mma.sync.aligned.m16n8k16.row.col.f32.bf16.bf16.f32 "
        "{%0,%1,%2,%3}, {%4,%5,%6,%7}, {%8,%9}, {%0,%1,%2,%3};"
        : "+f"(c[0]), "+f"(c[1]), "+f"(c[2]), "+f"(c[3])
        : "r"(a[0]), "r"(a[1]), "r"(a[2]), "r"(a[3]), "r"(b[0]), "r"(b[1]));
}

// ============================================================
// Kernel 1: QKV projection. q,k -> fp32 natural; v -> bf16 hi/lo split.
// ============================================================
__global__ __launch_bounds__(256) void qkv_kernel(const float* __restrict__ img,
                                                  const float* __restrict__ w,
                                                  const float* __restrict__ bias) {
    __shared__ float xs[32][128];
    __shared__ float ws[64][32];
    __shared__ float bs[64];

    const int b  = blockIdx.z;
    const int o0 = blockIdx.y * 64;
    const int n0 = blockIdx.x * 128;
    const int t  = threadIdx.x;

#pragma unroll
    for (int i = 0; i < 4; i++) {
        int idx = t + 256 * i;
        int c = idx >> 5, c4 = (idx & 31) << 2;
        *(float4*)&xs[c][c4] = *(const float4*)&img[((size_t)b * 32 + c) * 1024 + n0 + c4];
    }
#pragma unroll
    for (int i = 0; i < 2; i++) {
        int idx = t + 256 * i;
        int o = idx >> 3, c4 = (idx & 7) << 2;
        *(float4*)&ws[o][c4] = *(const float4*)&w[(size_t)(o0 + o) * 32 + c4];
    }
    if (t < 64) bs[t] = bias[o0 + t];
    __syncthreads();

    const int tx = t & 31;
    const int oy = t >> 5;

    float acc[8][4];
#pragma unroll
    for (int r = 0; r < 8; r++) {
        float bv = bs[8 * oy + r];
#pragma unroll
        for (int i = 0; i < 4; i++) acc[r][i] = bv;
    }
#pragma unroll
    for (int c = 0; c < 32; c++) {
        float4 x = *(const float4*)&xs[c][4 * tx];
#pragma unroll
        for (int r = 0; r < 8; r++) {
            float wv = ws[8 * oy + r][c];
            acc[r][0] += wv * x.x; acc[r][1] += wv * x.y;
            acc[r][2] += wv * x.z; acc[r][3] += wv * x.w;
        }
    }

    const int nglob = n0 + 4 * tx;
#pragma unroll
    for (int r = 0; r < 8; r++) {
        int o     = o0 + 8 * oy + r;
        int which = o >> 12;
        int oc    = o & 4095;
        int h     = oc & 3;
        int cch   = oc >> 2;
        size_t idx = (((size_t)b * 4 + h) << 20) + (size_t)cch * 1024 + nglob;
        if (which == 2) {
            __nv_bfloat16* Vh = (__nv_bfloat16*)g_Vh4;
            __nv_bfloat16* Vl = (__nv_bfloat16*)g_Vl4;
            __nv_bfloat162 p01 = __floats2bfloat162_rn(acc[r][0], acc[r][1]);
            __nv_bfloat162 p23 = __floats2bfloat162_rn(acc[r][2], acc[r][3]);
            uint2 hw; hw.x = *(unsigned*)&p01; hw.y = *(unsigned*)&p23;
            *(uint2*)&Vh[idx] = hw;
            float l0 = acc[r][0] - __low2float(p01);
            float l1 = acc[r][1] - __high2float(p01);
            float l2 = acc[r][2] - __low2float(p23);
            float l3 = acc[r][3] - __high2float(p23);
            uint2 lw; lw.x = packbf(l0, l1); lw.y = packbf(l2, l3);
            *(uint2*)&Vl[idx] = lw;
        } else {
            float* dst = (which == 0) ? g_Q : g_K;
            *(float4*)&dst[idx] = make_float4(acc[r][0], acc[r][1], acc[r][2], acc[r][3]);
        }
    }
}

// ============================================================
// Kernel 2: k softmax over n (row-wise) + bf16 hi/lo split, same [d][n] layout.
// ============================================================
__global__ __launch_bounds__(1024) void k_softmax_split_kernel() {
    const int z    = blockIdx.y;
    const int lane = threadIdx.x & 31;
    const int w    = threadIdx.x >> 5;
    const size_t rowoff = ((size_t)z << 20) + (size_t)(blockIdx.x * 32 + w) * 1024;
    const float* src = g_K + rowoff;

    float vals[32];
    float m = -3.402823466e38f;
#pragma unroll
    for (int j = 0; j < 32; j++) {
        vals[j] = src[j * 32 + lane];
        m = fmaxf(m, vals[j]);
    }
#pragma unroll
    for (int o = 16; o; o >>= 1) m = fmaxf(m, __shfl_xor_sync(0xffffffffu, m, o));
    float s = 0.f;
#pragma unroll
    for (int j = 0; j < 32; j++) { vals[j] = expf(vals[j] - m); s += vals[j]; }
#pragma unroll
    for (int o = 16; o; o >>= 1) s += __shfl_xor_sync(0xffffffffu, s, o);
    float inv = 1.f / s;

    __nv_bfloat16* Kh = (__nv_bfloat16*)g_Kh4 + rowoff;
    __nv_bfloat16* Kl = (__nv_bfloat16*)g_Kl4 + rowoff;
#pragma unroll
    for (int j = 0; j < 32; j++) {
        float v = vals[j] * inv;
        __nv_bfloat16 h = __float2bfloat16(v);
        Kh[j * 32 + lane] = h;
        Kl[j * 32 + lane] = __float2bfloat16(v - __bfloat162float(h));
    }
}

// ============================================================
// Kernel 3: q denominator: g_qinv[z][n] = SCALE / sum_d exp(q[d][n]).
// ============================================================
__global__ __launch_bounds__(256) void q_sum_kernel() {
    __shared__ float red[8][32];
    const int z  = blockIdx.y;
    const int nl = threadIdx.x & 31;
    const int dg = threadIdx.x >> 5;
    const int n  = blockIdx.x * 32 + nl;
    const float* src = g_Q + ((size_t)z << 20) + n;

    float s = 0.f;
#pragma unroll 8
    for (int d = dg * 128; d < dg * 128 + 128; d++) s += expf(src[(size_t)d * 1024]);
    red[dg][nl] = s;
    __syncthreads();
    if (dg == 0) {
        float tot = 0.f;
#pragma unroll
        for (int r = 0; r < 8; r++) tot += red[r][nl];
        g_qinv[z * 1024 + n] = SCALE / tot;
    }
}

// ============================================================
// Kernel 4: q softmax-apply + transpose + bf16 split -> qT[n][d] hi/lo.
// ============================================================
__global__ void q_t_split_kernel() {
    __shared__ float s[32][33];
    const int z  = blockIdx.z;
    const int d0 = blockIdx.y * 32;
    const int n0 = blockIdx.x * 32;
    const int tx = threadIdx.x, ty = threadIdx.y;
    const float* src = g_Q + ((size_t)z << 20);
    const float inv = g_qinv[z * 1024 + n0 + tx];

#pragma unroll
    for (int i = 0; i < 4; i++) {
        int r = ty + 8 * i;
        s[r][tx] = expf(src[(size_t)(d0 + r) * 1024 + n0 + tx]) * inv;
    }
    __syncthreads();

    __nv_bfloat16* Qh = (__nv_bfloat16*)g_Qh4 + ((size_t)z << 20);
    __nv_bfloat16* Ql = (__nv_bfloat16*)g_Ql4 + ((size_t)z << 20);
#pragma unroll
    for (int i = 0; i < 4; i++) {
        int nl = ty + 8 * i;
        float v = s[tx][nl];
        __nv_bfloat16 h = __float2bfloat16(v);
        size_t idx = (size_t)(n0 + nl) * 1024 + d0 + tx;
        Qh[idx] = h;
        Ql[idx] = __float2bfloat16(v - __bfloat162float(h));
    }
}

// ============================================================
// Kernel 5: bf16 split-precision TN GEMM via mma.sync (HMMA path,
// compiles for compute_100; no tcgen05 needed).
//   D[m,n'] = sum_k A[m,k]*B[n',k], both operands K-contiguous bf16,
//   3 passes Ah*Bh + Ah*Bl + Al*Bh into fp32 register accumulators.
// stage 0: A=V[e][n],  B=Ksm[d][n] -> CT[e][d]  (written bf16 hi/lo)
// stage 1: A=CT[e][d], B=QT[n][d]  -> X [e][n]  (written fp32)
// block 128x128, 8 warps (warp tile 64x32), K staged 64/iter,
// cp.async double-buffered SMEM (128KB), XOR-swizzled 128B rows.
// grid (8, 8, 16), block 256.
// ============================================================
#define GEMM_SMEM 131072

__global__ __launch_bounds__(256) void gemm_mma_kernel(int stage) {
    extern __shared__ char smem[];
    const uint32_t sbase = smem_u32(smem);
    const int t    = threadIdx.x;
    const int lane = t & 31;
    const int wid  = t >> 5;

    const __nv_bfloat16 *Ah, *Al, *Bh, *Bl;
    if (stage == 0) {
        Ah = (const __nv_bfloat16*)g_Vh4; Al = (const __nv_bfloat16*)g_Vl4;
        Bh = (const __nv_bfloat16*)g_Kh4; Bl = (const __nv_bfloat16*)g_Kl4;
    } else {
        Ah = (const __nv_bfloat16*)g_Ch4; Al = (const __nv_bfloat16*)g_Cl4;
        Bh = (const __nv_bfloat16*)g_Qh4; Bl = (const __nv_bfloat16*)g_Ql4;
    }
    const size_t zoff = (size_t)blockIdx.z << 20;
    const int m0 = blockIdx.y * 128;
    const int n0 = blockIdx.x * 128;

    // ---- loader mapping: thread -> row r (0..127), chunk group c0 (0 or 4)
    const int r  = t >> 1;
    const int c0 = (t & 1) * 4;
    const char* pAh = (const char*)(Ah + zoff + (size_t)(m0 + r) * 1024);
    const char* pAl = (const char*)(Al + zoff + (size_t)(m0 + r) * 1024);
    const char* pBh = (const char*)(Bh + zoff + (size_t)(n0 + r) * 1024);
    const char* pBl = (const char*)(Bl + zoff + (size_t)(n0 + r) * 1024);
    uint32_t so[4];
#pragma unroll
    for (int j = 0; j < 4; j++) so[j] = (uint32_t)(r * 128 + (((c0 + j) ^ (r & 7)) << 4));

    auto issue = [&](int kt, int buf) {
        const uint32_t sb = sbase + buf * 65536;
        const int gb = kt * 128 + c0 * 16;   // byte offset within row
#pragma unroll
        for (int j = 0; j < 4; j++) {
            cpasync16(sb +         so[j], pAh + gb + j * 16);
            cpasync16(sb + 16384 + so[j], pAl + gb + j * 16);
            cpasync16(sb + 32768 + so[j], pBh + gb + j * 16);
            cpasync16(sb + 49152 + so[j], pBl + gb + j * 16);
        }
        cp_commit();
    };

    // ---- compute mapping: warp tile 64x32; wm in {0,1}, wn in {0..3}
    const int wm = wid & 1;
    const int wn = wid >> 1;
    // A fragment row/chunk pieces (lane-dependent)
    const int aR  = wm * 64 + (lane & 15);      // + mb*16
    const int aHi = lane >> 4;                  // chunk bit
    // B fragment
    const int bR  = wn * 32 + (lane & 7) + ((lane >> 4) << 3);  // + np*16
    const int bHi = (lane >> 3) & 1;

    float acc[4][4][4];
#pragma unroll
    for (int i = 0; i < 4; i++)
#pragma unroll
        for (int j = 0; j < 4; j++)
#pragma unroll
            for (int p = 0; p < 4; p++) acc[i][j][p] = 0.f;

    issue(0, 0);

#pragma unroll 1
    for (int kt = 0; kt < 16; kt++) {
        const int buf = kt & 1;
        if (kt < 15) { issue(kt + 1, buf ^ 1); cp_wait1(); }
        else         { cp_wait0(); }
        __syncthreads();

        const uint32_t sb = sbase + buf * 65536;
#pragma unroll
        for (int ks = 0; ks < 4; ks++) {
            unsigned ah[4][4], al[4][4], bh[2][4], bl[2][4];
#pragma unroll
            for (int mb = 0; mb < 4; mb++) {
                int R  = aR + mb * 16;
                int ch = 2 * ks + aHi;
                uint32_t ad = sb + (R << 7) + (((ch ^ (R & 7))) << 4);
                ldsm4(ah[mb], ad);
                ldsm4(al[mb], ad + 16384);
            }
#pragma unroll
            for (int np = 0; np < 2; np++) {
                int R  = bR + np * 16;
                int ch = 2 * ks + bHi;
                uint32_t bd = sb + 32768 + (R << 7) + (((ch ^ (R & 7))) << 4);
                ldsm4(bh[np], bd);
                ldsm4(bl[np], bd + 16384);
            }
#pragma unroll
            for (int mb = 0; mb < 4; mb++)
#pragma unroll
                for (int nb = 0; nb < 4; nb++) {
                    const unsigned* bhp = &bh[nb >> 1][(nb & 1) * 2];
                    const unsigned* blp = &bl[nb >> 1][(nb & 1) * 2];
                    mma16816(acc[mb][nb], ah[mb], bhp);
                    mma16816(acc[mb][nb], ah[mb], blp);
                    mma16816(acc[mb][nb], al[mb], bhp);
                }
        }
        __syncthreads();
    }

    // ---- epilogue
    const int g  = lane >> 2;
    const int tt = lane & 3;
    const int mw = m0 + wm * 64;
    const int nw = n0 + wn * 32;

    if (stage == 0) {
        __nv_bfloat16* Ch = (__nv_bfloat16*)g_Ch4;
        __nv_bfloat16* Cl = (__nv_bfloat16*)g_Cl4;
#pragma unroll
        for (int mb = 0; mb < 4; mb++)
#pragma unroll
            for (int nb = 0; nb < 4; nb++) {
                const float* a = acc[mb][nb];
                size_t base = zoff + (size_t)(mw + mb * 16 + g) * 1024 + nw + nb * 8 + 2 * tt;
                __nv_bfloat162 hp0 = __floats2bfloat162_rn(a[0], a[1]);
                *(unsigned*)&Ch[base] = *(unsigned*)&hp0;
                *(unsigned*)&Cl[base] = packbf(a[0] - __low2float(hp0), a[1] - __high2float(hp0));
                __nv_bfloat162 hp1 = __floats2bfloat162_rn(a[2], a[3]);
                *(unsigned*)&Ch[base + 8 * 1024] = *(unsigned*)&hp1;
                *(unsigned*)&Cl[base + 8 * 1024] =
                    packbf(a[2] - __low2float(hp1), a[3] - __high2float(hp1));
            }
    } else {
#pragma unroll
        for (int mb = 0; mb < 4; mb++)
#pragma unroll
            for (int nb = 0; nb < 4; nb++) {
                const float* a = acc[mb][nb];
                size_t base = zoff + (size_t)(mw + mb * 16 + g) * 1024 + nw + nb * 8 + 2 * tt;
                *(float2*)&g_X[base]            = make_float2(a[0], a[1]);
                *(float2*)&g_X[base + 8 * 1024] = make_float2(a[2], a[3]);
            }
    }
}

// ============================================================
// Kernel 6: output projection. Y[b,o,n] = b_out[o] + sum_c X[b,c,n]*w_out[o,c]
// ============================================================
__global__ __launch_bounds__(256) void proj_kernel(const float* __restrict__ wout,
                                                   const float* __restrict__ bout) {
    __shared__ float ws[32][64];
    const int b  = blockIdx.y;
    const int n  = blockIdx.x * 32 + (threadIdx.x & 31);
    const int og = threadIdx.x >> 5;
    const float* X = g_X + ((size_t)b << 22);

    float acc[4];
#pragma unroll
    for (int j = 0; j < 4; j++) acc[j] = bout[og * 4 + j];

    for (int c0 = 0; c0 < 4096; c0 += 64) {
        __syncthreads();
#pragma unroll
        for (int i = 0; i < 2; i++) {
            int idx = threadIdx.x + 256 * i;
            int o = idx >> 4, c4 = (idx & 15) << 2;
            *(float4*)&ws[o][c4] = *(const float4*)&wout[(size_t)o * 4096 + c0 + c4];
        }
        __syncthreads();
#pragma unroll 16
        for (int cl = 0; cl < 64; cl++) {
            float x = X[(size_t)(c0 + cl) * 1024 + n];
#pragma unroll
            for (int j = 0; j < 4; j++) acc[j] += ws[og * 4 + j][cl] * x;
        }
    }
#pragma unroll
    for (int j = 0; j < 4; j++)
        g_Y[((size_t)b * 32 + og * 4 + j) * 1024 + n] = acc[j];
}

// ============================================================
// Kernel 7: per-batch mean/var.
// ============================================================
__global__ __launch_bounds__(1024) void stats_kernel() {
    __shared__ float ss[32], ss2[32];
    const int b = blockIdx.x, t = threadIdx.x;
    const float* Y = g_Y + (size_t)b * 32768;
    float s = 0.f, s2 = 0.f;
#pragma unroll
    for (int k = 0; k < 32; k++) {
        float v = Y[t + 1024 * k];
        s += v; s2 += v * v;
    }
#pragma unroll
    for (int o = 16; o; o >>= 1) {
        s  += __shfl_xor_sync(0xffffffffu, s, o);
        s2 += __shfl_xor_sync(0xffffffffu, s2, o);
    }
    if ((t & 31) == 0) { ss[t >> 5] = s; ss2[t >> 5] = s2; }
    __syncthreads();
    if (t < 32) {
        s = ss[t]; s2 = ss2[t];
#pragma unroll
        for (int o = 16; o; o >>= 1) {
            s  += __shfl_xor_sync(0xffffffffu, s, o);
            s2 += __shfl_xor_sync(0xffffffffu, s2, o);
        }
        if (t == 0) {
            float mean = s * (1.f / 32768.f);
            g_stats[b]     = mean;
            g_stats[4 + b] = s2 * (1.f / 32768.f) - mean * mean;
        }
    }
}

// ============================================================
// Kernel 8: GroupNorm finalize -> d_out.
// ============================================================
__global__ void gn_kernel(const float* __restrict__ gamma,
                          const float* __restrict__ beta,
                          float* __restrict__ out) {
    int idx = blockIdx.x * 256 + threadIdx.x;
    int b = idx >> 15;
    int o = (idx >> 10) & 31;
    float mean = g_stats[b];
    float rstd = rsqrtf(g_stats[4 + b] + EPSGN);
    out[idx] = (g_Y[idx] - mean) * rstd * gamma[o] + beta[o];
}

// ============================================================
extern "C" void kernel_launch(void* const* d_in, const int* in_sizes, int n_in,
                              void* d_out, int out_size) {
    (void)in_sizes; (void)n_in; (void)out_size;
    const float* image = (const float*)d_in[0];
    const float* w_qkv = (const float*)d_in[1];
    const float* b_qkv = (const float*)d_in[2];
    const float* w_out = (const float*)d_in[3];
    const float* b_out = (const float*)d_in[4];
    const float* gamma = (const float*)d_in[5];
    const float* beta  = (const float*)d_in[6];
    float* out = (float*)d_out;

    cudaFuncSetAttribute(gemm_mma_kernel,
                         cudaFuncAttributeMaxDynamicSharedMemorySize, GEMM_SMEM);

    qkv_kernel<<<dim3(8, 192, 4), 256>>>(image, w_qkv, b_qkv);
    k_softmax_split_kernel<<<dim3(32, 16), 1024>>>();
    q_sum_kernel<<<dim3(32, 16), 256>>>();
    q_t_split_kernel<<<dim3(32, 32, 16), dim3(32, 8)>>>();
    gemm_mma_kernel<<<dim3(8, 8, 16), 256, GEMM_SMEM>>>(0);  // CT = V * K^T
    gemm_mma_kernel<<<dim3(8, 8, 16), 256, GEMM_SMEM>>>(1);  // X  = CT * QT^T
    proj_kernel<<<dim3(32, 4), 256>>>(w_out, b_out);
    stats_kernel<<<4, 1024>>>();
    gn_kernel<<<512, 256>>>(gamma, beta, out);
}

// round 7
// speedup vs baseline: 1.7565x; 1.0772x over previous
#include <cuda_runtime.h>
#include <cuda_bf16.h>
#include <math.h>
#include <stdint.h>

// ---------------- problem constants ----------------
#define NB    4
#define NC    32
#define NSP   1024
#define ND    1024
#define NBH   16
#define SCALE 0.17677669529663687f   // 1/sqrt(32)
#define EPSGN 1e-5f

// ---------------- scratch (device globals; allocation-free) ----------------
__device__ float g_Q  [NBH * ND * NSP];       // q natural [bh][d][n] fp32 (pre-softmax)
__device__ float g_K  [NBH * ND * NSP];       // k natural [bh][d][n] fp32 (pre-softmax)
__device__ float g_X  [NBH * ND * NSP];       // attention out [bh][e][n] fp32
__device__ float g_Y  [NB * NC * NSP];        // projection out, pre-GN
__device__ float g_stats[8];                  // mean[4], var[4]
__device__ float g_qinv[NBH * NSP];           // SCALE / sum(exp(q)) per (z,n)

// bf16 hi/lo operand arrays (uint4-backed for 16B alignment)
#define BFN (NBH * ND * NSP / 8)
__device__ uint4 g_Vh4[BFN]; __device__ uint4 g_Vl4[BFN];   // v  [e][n]
__device__ uint4 g_Kh4[BFN]; __device__ uint4 g_Kl4[BFN];   // k softmaxed [d][n]
__device__ uint4 g_Qh4[BFN]; __device__ uint4 g_Ql4[BFN];   // qT softmaxed [n][d]
__device__ uint4 g_Ch4[BFN]; __device__ uint4 g_Cl4[BFN];   // ctx^T [e][d]

// ---------------- small helpers ----------------
__device__ __forceinline__ uint32_t smem_u32(const void* p) {
    uint32_t a;
    asm("{ .reg .u64 t; cvta.to.shared.u64 t, %1; cvt.u32.u64 %0, t; }" : "=r"(a) : "l"(p));
    return a;
}
__device__ __forceinline__ unsigned packbf(float a, float b) {
    __nv_bfloat162 p = __floats2bfloat162_rn(a, b);
    return *reinterpret_cast<unsigned*>(&p);
}
__device__ __forceinline__ void cpasync16(uint32_t saddr, const void* g) {
    asm volatile("cp.async.cg.shared.global [%0], [%1], 16;" :: "r"(saddr), "l"(g));
}
__device__ __forceinline__ void cp_commit() {
    asm volatile("cp.async.commit_group;" ::: "memory");
}
__device__ __forceinline__ void cp_wait1() {
    asm volatile("cp.async.wait_group 1;" ::: "memory");
}
__device__ __forceinline__ void cp_wait0() {
    asm volatile("cp.async.wait_group 0;" ::: "memory");
}
__device__ __forceinline__ void ldsm4(unsigned* r, uint32_t addr) {
    asm volatile("ldmatrix.sync.aligned.m8n8.x4.shared.b16 {%0,%1,%2,%3}, [%4];"
                 : "=r"(r[0]), "=r"(r[1]), "=r"(r[2]), "=r"(r[3]) : "r"(addr));
}
__device__ __forceinline__ void mma16816(float* c, const unsigned* a, const unsigned* b) {
    asm volatile(
        "mma.sync.aligned.m16n8k16.row.col.f32.bf16.bf16.f32 "
        "{%0,%1,%2,%3}, {%4,%5,%6,%7}, {%8,%9}, {%0,%1,%2,%3};"
        : "+f"(c[0]), "+f"(c[1]), "+f"(c[2]), "+f"(c[3])
        : "r"(a[0]), "r"(a[1]), "r"(a[2]), "r"(a[3]), "r"(b[0]), "r"(b[1]));
}
// conflict-free swizzle for 64B rows, 4 chunks of 16B:
// bank-group(R,ch) = (4R + s) mod 8 with s = (ch + (R>>1)) & 3 -> 8 distinct
// groups across any 8 consecutive rows at fixed ch (ldmatrix phase = floor).
__device__ __forceinline__ uint32_t swzoff(int R, int ch) {
    return (uint32_t)(R * 64 + (((ch + (R >> 1)) & 3) << 4));
}

// ============================================================
// Kernel 1: QKV projection. q,k -> fp32 natural; v -> bf16 hi/lo split.
// ============================================================
__global__ __launch_bounds__(256) void qkv_kernel(const float* __restrict__ img,
                                                  const float* __restrict__ w,
                                                  const float* __restrict__ bias) {
    __shared__ float xs[32][128];
    __shared__ float ws[64][32];
    __shared__ float bs[64];

    const int b  = blockIdx.z;
    const int o0 = blockIdx.y * 64;
    const int n0 = blockIdx.x * 128;
    const int t  = threadIdx.x;

#pragma unroll
    for (int i = 0; i < 4; i++) {
        int idx = t + 256 * i;
        int c = idx >> 5, c4 = (idx & 31) << 2;
        *(float4*)&xs[c][c4] = *(const float4*)&img[((size_t)b * 32 + c) * 1024 + n0 + c4];
    }
#pragma unroll
    for (int i = 0; i < 2; i++) {
        int idx = t + 256 * i;
        int o = idx >> 3, c4 = (idx & 7) << 2;
        *(float4*)&ws[o][c4] = *(const float4*)&w[(size_t)(o0 + o) * 32 + c4];
    }
    if (t < 64) bs[t] = bias[o0 + t];
    __syncthreads();

    const int tx = t & 31;
    const int oy = t >> 5;

    float acc[8][4];
#pragma unroll
    for (int r = 0; r < 8; r++) {
        float bv = bs[8 * oy + r];
#pragma unroll
        for (int i = 0; i < 4; i++) acc[r][i] = bv;
    }
#pragma unroll
    for (int c = 0; c < 32; c++) {
        float4 x = *(const float4*)&xs[c][4 * tx];
#pragma unroll
        for (int r = 0; r < 8; r++) {
            float wv = ws[8 * oy + r][c];
            acc[r][0] += wv * x.x; acc[r][1] += wv * x.y;
            acc[r][2] += wv * x.z; acc[r][3] += wv * x.w;
        }
    }

    const int nglob = n0 + 4 * tx;
#pragma unroll
    for (int r = 0; r < 8; r++) {
        int o     = o0 + 8 * oy + r;
        int which = o >> 12;
        int oc    = o & 4095;
        int h     = oc & 3;
        int cch   = oc >> 2;
        size_t idx = (((size_t)b * 4 + h) << 20) + (size_t)cch * 1024 + nglob;
        if (which == 2) {
            __nv_bfloat16* Vh = (__nv_bfloat16*)g_Vh4;
            __nv_bfloat16* Vl = (__nv_bfloat16*)g_Vl4;
            __nv_bfloat162 p01 = __floats2bfloat162_rn(acc[r][0], acc[r][1]);
            __nv_bfloat162 p23 = __floats2bfloat162_rn(acc[r][2], acc[r][3]);
            uint2 hw; hw.x = *(unsigned*)&p01; hw.y = *(unsigned*)&p23;
            *(uint2*)&Vh[idx] = hw;
            float l0 = acc[r][0] - __low2float(p01);
            float l1 = acc[r][1] - __high2float(p01);
            float l2 = acc[r][2] - __low2float(p23);
            float l3 = acc[r][3] - __high2float(p23);
            uint2 lw; lw.x = packbf(l0, l1); lw.y = packbf(l2, l3);
            *(uint2*)&Vl[idx] = lw;
        } else {
            float* dst = (which == 0) ? g_Q : g_K;
            *(float4*)&dst[idx] = make_float4(acc[r][0], acc[r][1], acc[r][2], acc[r][3]);
        }
    }
}

// ============================================================
// Kernel 2: k softmax over n (row-wise) + bf16 hi/lo split.
// ============================================================
__global__ __launch_bounds__(1024) void k_softmax_split_kernel() {
    const int z    = blockIdx.y;
    const int lane = threadIdx.x & 31;
    const int w    = threadIdx.x >> 5;
    const size_t rowoff = ((size_t)z << 20) + (size_t)(blockIdx.x * 32 + w) * 1024;
    const float* src = g_K + rowoff;

    float vals[32];
    float m = -3.402823466e38f;
#pragma unroll
    for (int j = 0; j < 32; j++) {
        vals[j] = src[j * 32 + lane];
        m = fmaxf(m, vals[j]);
    }
#pragma unroll
    for (int o = 16; o; o >>= 1) m = fmaxf(m, __shfl_xor_sync(0xffffffffu, m, o));
    float s = 0.f;
#pragma unroll
    for (int j = 0; j < 32; j++) { vals[j] = expf(vals[j] - m); s += vals[j]; }
#pragma unroll
    for (int o = 16; o; o >>= 1) s += __shfl_xor_sync(0xffffffffu, s, o);
    float inv = 1.f / s;

    __nv_bfloat16* Kh = (__nv_bfloat16*)g_Kh4 + rowoff;
    __nv_bfloat16* Kl = (__nv_bfloat16*)g_Kl4 + rowoff;
#pragma unroll
    for (int j = 0; j < 32; j++) {
        float v = vals[j] * inv;
        __nv_bfloat16 h = __float2bfloat16(v);
        Kh[j * 32 + lane] = h;
        Kl[j * 32 + lane] = __float2bfloat16(v - __bfloat162float(h));
    }
}

// ============================================================
// Kernel 3: q denominator: g_qinv[z][n] = SCALE / sum_d exp(q[d][n]).
// ============================================================
__global__ __launch_bounds__(256) void q_sum_kernel() {
    __shared__ float red[8][32];
    const int z  = blockIdx.y;
    const int nl = threadIdx.x & 31;
    const int dg = threadIdx.x >> 5;
    const int n  = blockIdx.x * 32 + nl;
    const float* src = g_Q + ((size_t)z << 20) + n;

    float s = 0.f;
#pragma unroll 8
    for (int d = dg * 128; d < dg * 128 + 128; d++) s += expf(src[(size_t)d * 1024]);
    red[dg][nl] = s;
    __syncthreads();
    if (dg == 0) {
        float tot = 0.f;
#pragma unroll
        for (int r = 0; r < 8; r++) tot += red[r][nl];
        g_qinv[z * 1024 + n] = SCALE / tot;
    }
}

// ============================================================
// Kernel 4: q softmax-apply + transpose + bf16 split -> qT[n][d] hi/lo.
// ============================================================
__global__ void q_t_split_kernel() {
    __shared__ float s[32][33];
    const int z  = blockIdx.z;
    const int d0 = blockIdx.y * 32;
    const int n0 = blockIdx.x * 32;
    const int tx = threadIdx.x, ty = threadIdx.y;
    const float* src = g_Q + ((size_t)z << 20);
    const float inv = g_qinv[z * 1024 + n0 + tx];

#pragma unroll
    for (int i = 0; i < 4; i++) {
        int r = ty + 8 * i;
        s[r][tx] = expf(src[(size_t)(d0 + r) * 1024 + n0 + tx]) * inv;
    }
    __syncthreads();

    __nv_bfloat16* Qh = (__nv_bfloat16*)g_Qh4 + ((size_t)z << 20);
    __nv_bfloat16* Ql = (__nv_bfloat16*)g_Ql4 + ((size_t)z << 20);
#pragma unroll
    for (int i = 0; i < 4; i++) {
        int nl = ty + 8 * i;
        float v = s[tx][nl];
        __nv_bfloat16 h = __float2bfloat16(v);
        size_t idx = (size_t)(n0 + nl) * 1024 + d0 + tx;
        Qh[idx] = h;
        Ql[idx] = __float2bfloat16(v - __bfloat162float(h));
    }
}

// ============================================================
// Kernel 5: bf16 split-precision TN GEMM via mma.sync.
//   D[m,n'] = sum_k A[m,k]*B[n',k], 3 passes Ah*Bh + Ah*Bl + Al*Bh.
// stage 0: A=V[e][n],  B=Ksm[d][n] -> CT[e][d]  (written bf16 hi/lo)
// stage 1: A=CT[e][d], B=QT[n][d]  -> X [e][n]  (written fp32)
// block 128x128, 8 warps (warp tile 64x32), K staged 32/chunk,
// 3-stage cp.async ring (96KB smem -> 2 CTAs/SM), 1 sync per chunk.
// grid (8, 8, 16), block 256.
// ============================================================
#define GEMM_SMEM (3 * 32768)

__global__ __launch_bounds__(256, 2) void gemm_mma_kernel(int stage) {
    extern __shared__ char smem[];
    const uint32_t sbase = smem_u32(smem);
    const int t    = threadIdx.x;
    const int lane = t & 31;
    const int wid  = t >> 5;

    const __nv_bfloat16 *Ah, *Al, *Bh, *Bl;
    if (stage == 0) {
        Ah = (const __nv_bfloat16*)g_Vh4; Al = (const __nv_bfloat16*)g_Vl4;
        Bh = (const __nv_bfloat16*)g_Kh4; Bl = (const __nv_bfloat16*)g_Kl4;
    } else {
        Ah = (const __nv_bfloat16*)g_Ch4; Al = (const __nv_bfloat16*)g_Cl4;
        Bh = (const __nv_bfloat16*)g_Qh4; Bl = (const __nv_bfloat16*)g_Ql4;
    }
    const size_t zoff = (size_t)blockIdx.z << 20;
    const int m0 = blockIdx.y * 128;
    const int n0 = blockIdx.x * 128;

    // ---- loader mapping: thread -> row r (0..127), chunks c0, c0+1
    const int r  = t >> 1;
    const int c0 = (t & 1) * 2;
    const char* pAh = (const char*)(Ah + zoff + (size_t)(m0 + r) * 1024);
    const char* pAl = (const char*)(Al + zoff + (size_t)(m0 + r) * 1024);
    const char* pBh = (const char*)(Bh + zoff + (size_t)(n0 + r) * 1024);
    const char* pBl = (const char*)(Bl + zoff + (size_t)(n0 + r) * 1024);
    uint32_t so0 = swzoff(r, c0);
    uint32_t so1 = swzoff(r, c0 + 1);

    // stage layout (32KB): Ah @0, Al @8K, Bh @16K, Bl @24K
    auto issue = [&](int kt, int st) {
        const uint32_t sb = sbase + st * 32768;
        const int gb = kt * 64 + c0 * 16;  // global byte offset within row
        cpasync16(sb +         so0, pAh + gb);
        cpasync16(sb +         so1, pAh + gb + 16);
        cpasync16(sb +  8192 + so0, pAl + gb);
        cpasync16(sb +  8192 + so1, pAl + gb + 16);
        cpasync16(sb + 16384 + so0, pBh + gb);
        cpasync16(sb + 16384 + so1, pBh + gb + 16);
        cpasync16(sb + 24576 + so0, pBl + gb);
        cpasync16(sb + 24576 + so1, pBl + gb + 16);
        cp_commit();
    };

    // ---- compute mapping: warp tile 64x32; wm in {0,1}, wn in {0..3}
    const int wm = wid & 1;
    const int wn = wid >> 1;
    const int aR  = wm * 64 + (lane & 15);
    const int aHi = lane >> 4;
    const int bR  = wn * 32 + (lane & 7) + ((lane >> 4) << 3);
    const int bHi = (lane >> 3) & 1;

    float acc[4][4][4];
#pragma unroll
    for (int i = 0; i < 4; i++)
#pragma unroll
        for (int j = 0; j < 4; j++)
#pragma unroll
            for (int p = 0; p < 4; p++) acc[i][j][p] = 0.f;

    issue(0, 0);
    issue(1, 1);

#pragma unroll 1
    for (int kt = 0; kt < 32; kt++) {
        if (kt >= 30) cp_wait0(); else cp_wait1();
        __syncthreads();
        // refill the stage everyone just finished (kt-1's stage) with kt+2
        if (kt + 2 < 32) issue(kt + 2, (kt + 2) % 3);

        const uint32_t sb = sbase + (kt % 3) * 32768;
#pragma unroll
        for (int ks = 0; ks < 2; ks++) {
            unsigned bh[2][4], bl[2][4];
#pragma unroll
            for (int np = 0; np < 2; np++) {
                int R  = bR + np * 16;
                int ch = 2 * ks + bHi;
                uint32_t bd = sb + 16384 + swzoff(R, ch);
                ldsm4(bh[np], bd);
                ldsm4(bl[np], bd + 8192);
            }
#pragma unroll
            for (int mb = 0; mb < 4; mb++) {
                unsigned ah[4], al[4];
                int R  = aR + mb * 16;
                int ch = 2 * ks + aHi;
                uint32_t ad = sb + swzoff(R, ch);
                ldsm4(ah, ad);
                ldsm4(al, ad + 8192);
#pragma unroll
                for (int nb = 0; nb < 4; nb++) {
                    const unsigned* bhp = &bh[nb >> 1][(nb & 1) * 2];
                    const unsigned* blp = &bl[nb >> 1][(nb & 1) * 2];
                    mma16816(acc[mb][nb], ah, bhp);
                    mma16816(acc[mb][nb], ah, blp);
                    mma16816(acc[mb][nb], al, bhp);
                }
            }
        }
    }

    // ---- epilogue
    const int g  = lane >> 2;
    const int tt = lane & 3;
    const int mw = m0 + wm * 64;
    const int nw = n0 + wn * 32;

    if (stage == 0) {
        __nv_bfloat16* Ch = (__nv_bfloat16*)g_Ch4;
        __nv_bfloat16* Cl = (__nv_bfloat16*)g_Cl4;
#pragma unroll
        for (int mb = 0; mb < 4; mb++)
#pragma unroll
            for (int nb = 0; nb < 4; nb++) {
                const float* a = acc[mb][nb];
                size_t base = zoff + (size_t)(mw + mb * 16 + g) * 1024 + nw + nb * 8 + 2 * tt;
                __nv_bfloat162 hp0 = __floats2bfloat162_rn(a[0], a[1]);
                *(unsigned*)&Ch[base] = *(unsigned*)&hp0;
                *(unsigned*)&Cl[base] = packbf(a[0] - __low2float(hp0), a[1] - __high2float(hp0));
                __nv_bfloat162 hp1 = __floats2bfloat162_rn(a[2], a[3]);
                *(unsigned*)&Ch[base + 8 * 1024] = *(unsigned*)&hp1;
                *(unsigned*)&Cl[base + 8 * 1024] =
                    packbf(a[2] - __low2float(hp1), a[3] - __high2float(hp1));
            }
    } else {
#pragma unroll
        for (int mb = 0; mb < 4; mb++)
#pragma unroll
            for (int nb = 0; nb < 4; nb++) {
                const float* a = acc[mb][nb];
                size_t base = zoff + (size_t)(mw + mb * 16 + g) * 1024 + nw + nb * 8 + 2 * tt;
                *(float2*)&g_X[base]            = make_float2(a[0], a[1]);
                *(float2*)&g_X[base + 8 * 1024] = make_float2(a[2], a[3]);
            }
    }
}

// ============================================================
// Kernel 6: output projection. Y[b,o,n] = b_out[o] + sum_c X[b,c,n]*w_out[o,c]
// ============================================================
__global__ __launch_bounds__(256) void proj_kernel(const float* __restrict__ wout,
                                                   const float* __restrict__ bout) {
    __shared__ float ws[32][64];
    const int b  = blockIdx.y;
    const int n  = blockIdx.x * 32 + (threadIdx.x & 31);
    const int og = threadIdx.x >> 5;
    const float* X = g_X + ((size_t)b << 22);

    float acc[4];
#pragma unroll
    for (int j = 0; j < 4; j++) acc[j] = bout[og * 4 + j];

    for (int c0 = 0; c0 < 4096; c0 += 64) {
        __syncthreads();
#pragma unroll
        for (int i = 0; i < 2; i++) {
            int idx = threadIdx.x + 256 * i;
            int o = idx >> 4, c4 = (idx & 15) << 2;
            *(float4*)&ws[o][c4] = *(const float4*)&wout[(size_t)o * 4096 + c0 + c4];
        }
        __syncthreads();
#pragma unroll 16
        for (int cl = 0; cl < 64; cl++) {
            float x = X[(size_t)(c0 + cl) * 1024 + n];
#pragma unroll
            for (int j = 0; j < 4; j++) acc[j] += ws[og * 4 + j][cl] * x;
        }
    }
#pragma unroll
    for (int j = 0; j < 4; j++)
        g_Y[((size_t)b * 32 + og * 4 + j) * 1024 + n] = acc[j];
}

// ============================================================
// Kernel 7: per-batch mean/var.
// ============================================================
__global__ __launch_bounds__(1024) void stats_kernel() {
    __shared__ float ss[32], ss2[32];
    const int b = blockIdx.x, t = threadIdx.x;
    const float* Y = g_Y + (size_t)b * 32768;
    float s = 0.f, s2 = 0.f;
#pragma unroll
    for (int k = 0; k < 32; k++) {
        float v = Y[t + 1024 * k];
        s += v; s2 += v * v;
    }
#pragma unroll
    for (int o = 16; o; o >>= 1) {
        s  += __shfl_xor_sync(0xffffffffu, s, o);
        s2 += __shfl_xor_sync(0xffffffffu, s2, o);
    }
    if ((t & 31) == 0) { ss[t >> 5] = s; ss2[t >> 5] = s2; }
    __syncthreads();
    if (t < 32) {
        s = ss[t]; s2 = ss2[t];
#pragma unroll
        for (int o = 16; o; o >>= 1) {
            s  += __shfl_xor_sync(0xffffffffu, s, o);
            s2 += __shfl_xor_sync(0xffffffffu, s2, o);
        }
        if (t == 0) {
            float mean = s * (1.f / 32768.f);
            g_stats[b]     = mean;
            g_stats[4 + b] = s2 * (1.f / 32768.f) - mean * mean;
        }
    }
}

// ============================================================
// Kernel 8: GroupNorm finalize -> d_out.
// ============================================================
__global__ void gn_kernel(const float* __restrict__ gamma,
                          const float* __restrict__ beta,
                          float* __restrict__ out) {
    int idx = blockIdx.x * 256 + threadIdx.x;
    int b = idx >> 15;
    int o = (idx >> 10) & 31;
    float mean = g_stats[b];
    float rstd = rsqrtf(g_stats[4 + b] + EPSGN);
    out[idx] = (g_Y[idx] - mean) * rstd * gamma[o] + beta[o];
}

// ============================================================
extern "C" void kernel_launch(void* const* d_in, const int* in_sizes, int n_in,
                              void* d_out, int out_size) {
    (void)in_sizes; (void)n_in; (void)out_size;
    const float* image = (const float*)d_in[0];
    const float* w_qkv = (const float*)d_in[1];
    const float* b_qkv = (const float*)d_in[2];
    const float* w_out = (const float*)d_in[3];
    const float* b_out = (const float*)d_in[4];
    const float* gamma = (const float*)d_in[5];
    const float* beta  = (const float*)d_in[6];
    float* out = (float*)d_out;

    cudaFuncSetAttribute(gemm_mma_kernel,
                         cudaFuncAttributeMaxDynamicSharedMemorySize, GEMM_SMEM);

    qkv_kernel<<<dim3(8, 192, 4), 256>>>(image, w_qkv, b_qkv);
    k_softmax_split_kernel<<<dim3(32, 16), 1024>>>();
    q_sum_kernel<<<dim3(32, 16), 256>>>();
    q_t_split_kernel<<<dim3(32, 32, 16), dim3(32, 8)>>>();
    gemm_mma_kernel<<<dim3(8, 8, 16), 256, GEMM_SMEM>>>(0);  // CT = V * K^T
    gemm_mma_kernel<<<dim3(8, 8, 16), 256, GEMM_SMEM>>>(1);  // X  = CT * QT^T
    proj_kernel<<<dim3(32, 4), 256>>>(w_out, b_out);
    stats_kernel<<<4, 1024>>>();
    gn_kernel<<<512, 256>>>(gamma, beta, out);
}

// round 8
// speedup vs baseline: 2.0696x; 1.1783x over previous
#include <cuda_runtime.h>
#include <cuda_fp16.h>
#include <math.h>
#include <stdint.h>

// ---------------- problem constants ----------------
#define NB    4
#define NC    32
#define NSP   1024
#define ND    1024
#define NBH   16
#define SCALE 0.17677669529663687f   // 1/sqrt(32)
#define EPSGN 1e-5f

// ---------------- scratch (device globals; allocation-free) ----------------
__device__ float g_Q  [NBH * ND * NSP];       // q natural [bh][d][n] fp32 (pre-softmax)
__device__ float g_K  [NBH * ND * NSP];       // k natural [bh][d][n] fp32 (pre-softmax)
__device__ float g_X  [NBH * ND * NSP];       // attention out [bh][e][n] fp32
__device__ float g_Y  [NB * NC * NSP];        // projection out, pre-GN
__device__ float g_stats[8];                  // mean[4], var[4]
__device__ float g_qinv[NBH * NSP];           // 256 / sum(exp(q)) per (z,n)

// f16 operand arrays (uint4-backed for 16B alignment)
#define HFN (NBH * ND * NSP / 8)
__device__ uint4 g_Vf4[HFN];                      // v  [e][n]            f16
__device__ uint4 g_Kh4[HFN]; __device__ uint4 g_Kl4[HFN];  // 256*k-softmax [d][n] hi/lo
__device__ uint4 g_Qh4[HFN]; __device__ uint4 g_Ql4[HFN];  // 256*q-softmax^T [n][d] hi/lo
__device__ uint4 g_Cf4[HFN];                      // ctx^T [e][d]         f16

// ---------------- small helpers ----------------
__device__ __forceinline__ uint32_t smem_u32(const void* p) {
    uint32_t a;
    asm("{ .reg .u64 t; cvta.to.shared.u64 t, %1; cvt.u32.u64 %0, t; }" : "=r"(a) : "l"(p));
    return a;
}
__device__ __forceinline__ unsigned packh2(float a, float b) {
    __half2 p = __floats2half2_rn(a, b);
    return *reinterpret_cast<unsigned*>(&p);
}
__device__ __forceinline__ void cpasync16(uint32_t saddr, const void* g) {
    asm volatile("cp.async.cg.shared.global [%0], [%1], 16;" :: "r"(saddr), "l"(g));
}
__device__ __forceinline__ void cp_commit() {
    asm volatile("cp.async.commit_group;" ::: "memory");
}
__device__ __forceinline__ void cp_wait2() {
    asm volatile("cp.async.wait_group 2;" ::: "memory");
}
__device__ __forceinline__ void cp_wait1() {
    asm volatile("cp.async.wait_group 1;" ::: "memory");
}
__device__ __forceinline__ void cp_wait0() {
    asm volatile("cp.async.wait_group 0;" ::: "memory");
}
__device__ __forceinline__ void ldsm4(unsigned* r, uint32_t addr) {
    asm volatile("ldmatrix.sync.aligned.m8n8.x4.shared.b16 {%0,%1,%2,%3}, [%4];"
                 : "=r"(r[0]), "=r"(r[1]), "=r"(r[2]), "=r"(r[3]) : "r"(addr));
}
__device__ __forceinline__ void mma16816(float* c, const unsigned* a, const unsigned* b) {
    asm volatile(
        "mma.sync.aligned.m16n8k16.row.col.f32.f16.f16.f32 "
        "{%0,%1,%2,%3}, {%4,%5,%6,%7}, {%8,%9}, {%0,%1,%2,%3};"
        : "+f"(c[0]), "+f"(c[1]), "+f"(c[2]), "+f"(c[3])
        : "r"(a[0]), "r"(a[1]), "r"(a[2]), "r"(a[3]), "r"(b[0]), "r"(b[1]));
}
// conflict-free swizzle for 64B rows, 4 chunks of 16B (validated in R6).
__device__ __forceinline__ uint32_t swzoff(int R, int ch) {
    return (uint32_t)(R * 64 + (((ch + (R >> 1)) & 3) << 4));
}

// ============================================================
// Kernel 1: QKV projection. q,k -> fp32 natural; v -> f16 single.
// ============================================================
__global__ __launch_bounds__(256) void qkv_kernel(const float* __restrict__ img,
                                                  const float* __restrict__ w,
                                                  const float* __restrict__ bias) {
    __shared__ float xs[32][128];
    __shared__ float ws[64][32];
    __shared__ float bs[64];

    const int b  = blockIdx.z;
    const int o0 = blockIdx.y * 64;
    const int n0 = blockIdx.x * 128;
    const int t  = threadIdx.x;

#pragma unroll
    for (int i = 0; i < 4; i++) {
        int idx = t + 256 * i;
        int c = idx >> 5, c4 = (idx & 31) << 2;
        *(float4*)&xs[c][c4] = *(const float4*)&img[((size_t)b * 32 + c) * 1024 + n0 + c4];
    }
#pragma unroll
    for (int i = 0; i < 2; i++) {
        int idx = t + 256 * i;
        int o = idx >> 3, c4 = (idx & 7) << 2;
        *(float4*)&ws[o][c4] = *(const float4*)&w[(size_t)(o0 + o) * 32 + c4];
    }
    if (t < 64) bs[t] = bias[o0 + t];
    __syncthreads();

    const int tx = t & 31;
    const int oy = t >> 5;

    float acc[8][4];
#pragma unroll
    for (int r = 0; r < 8; r++) {
        float bv = bs[8 * oy + r];
#pragma unroll
        for (int i = 0; i < 4; i++) acc[r][i] = bv;
    }
#pragma unroll
    for (int c = 0; c < 32; c++) {
        float4 x = *(const float4*)&xs[c][4 * tx];
#pragma unroll
        for (int r = 0; r < 8; r++) {
            float wv = ws[8 * oy + r][c];
            acc[r][0] += wv * x.x; acc[r][1] += wv * x.y;
            acc[r][2] += wv * x.z; acc[r][3] += wv * x.w;
        }
    }

    const int nglob = n0 + 4 * tx;
#pragma unroll
    for (int r = 0; r < 8; r++) {
        int o     = o0 + 8 * oy + r;
        int which = o >> 12;
        int oc    = o & 4095;
        int h     = oc & 3;
        int cch   = oc >> 2;
        size_t idx = (((size_t)b * 4 + h) << 20) + (size_t)cch * 1024 + nglob;
        if (which == 2) {
            __half* Vf = (__half*)g_Vf4;
            uint2 hv;
            hv.x = packh2(acc[r][0], acc[r][1]);
            hv.y = packh2(acc[r][2], acc[r][3]);
            *(uint2*)&Vf[idx] = hv;
        } else {
            float* dst = (which == 0) ? g_Q : g_K;
            *(float4*)&dst[idx] = make_float4(acc[r][0], acc[r][1], acc[r][2], acc[r][3]);
        }
    }
}

// ============================================================
// Kernel 2: k softmax over n (row-wise), ×256, f16 hi/lo split.
// ============================================================
__global__ __launch_bounds__(1024) void k_softmax_split_kernel() {
    const int z    = blockIdx.y;
    const int lane = threadIdx.x & 31;
    const int w    = threadIdx.x >> 5;
    const size_t rowoff = ((size_t)z << 20) + (size_t)(blockIdx.x * 32 + w) * 1024;
    const float* src = g_K + rowoff;

    float vals[32];
    float m = -3.402823466e38f;
#pragma unroll
    for (int j = 0; j < 32; j++) {
        vals[j] = src[j * 32 + lane];
        m = fmaxf(m, vals[j]);
    }
#pragma unroll
    for (int o = 16; o; o >>= 1) m = fmaxf(m, __shfl_xor_sync(0xffffffffu, m, o));
    float s = 0.f;
#pragma unroll
    for (int j = 0; j < 32; j++) { vals[j] = expf(vals[j] - m); s += vals[j]; }
#pragma unroll
    for (int o = 16; o; o >>= 1) s += __shfl_xor_sync(0xffffffffu, s, o);
    float inv = 256.f / s;

    __half* Kh = (__half*)g_Kh4 + rowoff;
    __half* Kl = (__half*)g_Kl4 + rowoff;
#pragma unroll
    for (int j = 0; j < 32; j++) {
        float v = vals[j] * inv;
        __half h = __float2half_rn(v);
        Kh[j * 32 + lane] = h;
        Kl[j * 32 + lane] = __float2half_rn(v - __half2float(h));
    }
}

// ============================================================
// Kernel 3: q denominator: g_qinv[z][n] = 256 / sum_d exp(q[d][n]).
// ============================================================
__global__ __launch_bounds__(256) void q_sum_kernel() {
    __shared__ float red[8][32];
    const int z  = blockIdx.y;
    const int nl = threadIdx.x & 31;
    const int dg = threadIdx.x >> 5;
    const int n  = blockIdx.x * 32 + nl;
    const float* src = g_Q + ((size_t)z << 20) + n;

    float s = 0.f;
#pragma unroll 8
    for (int d = dg * 128; d < dg * 128 + 128; d++) s += expf(src[(size_t)d * 1024]);
    red[dg][nl] = s;
    __syncthreads();
    if (dg == 0) {
        float tot = 0.f;
#pragma unroll
        for (int r = 0; r < 8; r++) tot += red[r][nl];
        g_qinv[z * 1024 + n] = 256.f / tot;
    }
}

// ============================================================
// Kernel 4: q softmax-apply (×256) + transpose + f16 split -> qT[n][d] hi/lo.
// ============================================================
__global__ void q_t_split_kernel() {
    __shared__ float s[32][33];
    const int z  = blockIdx.z;
    const int d0 = blockIdx.y * 32;
    const int n0 = blockIdx.x * 32;
    const int tx = threadIdx.x, ty = threadIdx.y;
    const float* src = g_Q + ((size_t)z << 20);
    const float inv = g_qinv[z * 1024 + n0 + tx];

#pragma unroll
    for (int i = 0; i < 4; i++) {
        int r = ty + 8 * i;
        s[r][tx] = expf(src[(size_t)(d0 + r) * 1024 + n0 + tx]) * inv;
    }
    __syncthreads();

    __half* Qh = (__half*)g_Qh4 + ((size_t)z << 20);
    __half* Ql = (__half*)g_Ql4 + ((size_t)z << 20);
#pragma unroll
    for (int i = 0; i < 4; i++) {
        int nl = ty + 8 * i;
        float v = s[tx][nl];
        __half h = __float2half_rn(v);
        size_t idx = (size_t)(n0 + nl) * 1024 + d0 + tx;
        Qh[idx] = h;
        Ql[idx] = __float2half_rn(v - __half2float(h));
    }
}

// ============================================================
// Kernel 5: f16 2-pass split TN GEMM via mma.sync.
//   D[m,n'] = sum_k A[m,k]*(Bh[n',k]+Bl[n',k]);   error = A_res*B ~2^-11.
// stage 0: A=Vf,  B={Kh,Kl} (256x) -> Cf[e][d] f16, scale 1/256
// stage 1: A=Cf,  B={Qh,Ql} (256x) -> X [e][n] fp32, scale SCALE/256
// block 128x128, 8 warps (warp tile 64x32), K staged 32/chunk,
// 4-stage cp.async ring (96KB smem, 2 CTAs/SM), 1 sync per chunk.
// grid (8, 8, 16), block 256.
// ============================================================
#define STAGE_BYTES 24576
#define GEMM_SMEM   (4 * STAGE_BYTES)

__global__ __launch_bounds__(256, 2) void gemm_mma_kernel(int stage) {
    extern __shared__ char smem[];
    const uint32_t sbase = smem_u32(smem);
    const int t    = threadIdx.x;
    const int lane = t & 31;
    const int wid  = t >> 5;

    const __half *A, *Bh, *Bl;
    if (stage == 0) {
        A  = (const __half*)g_Vf4;
        Bh = (const __half*)g_Kh4; Bl = (const __half*)g_Kl4;
    } else {
        A  = (const __half*)g_Cf4;
        Bh = (const __half*)g_Qh4; Bl = (const __half*)g_Ql4;
    }
    const size_t zoff = (size_t)blockIdx.z << 20;
    const int m0 = blockIdx.y * 128;
    const int n0 = blockIdx.x * 128;

    // ---- loader mapping: thread -> row r (0..127), chunks c0, c0+1
    const int r  = t >> 1;
    const int c0 = (t & 1) * 2;
    const char* pA  = (const char*)(A  + zoff + (size_t)(m0 + r) * 1024);
    const char* pBh = (const char*)(Bh + zoff + (size_t)(n0 + r) * 1024);
    const char* pBl = (const char*)(Bl + zoff + (size_t)(n0 + r) * 1024);
    const uint32_t so0 = swzoff(r, c0);
    const uint32_t so1 = swzoff(r, c0 + 1);

    // stage layout (24KB): A @0, Bh @8K, Bl @16K
    auto issue = [&](int kt) {
        const uint32_t sb = sbase + (kt & 3) * STAGE_BYTES;
        const int gb = kt * 64 + c0 * 16;  // global byte offset within row
        cpasync16(sb +         so0, pA  + gb);
        cpasync16(sb +         so1, pA  + gb + 16);
        cpasync16(sb +  8192 + so0, pBh + gb);
        cpasync16(sb +  8192 + so1, pBh + gb + 16);
        cpasync16(sb + 16384 + so0, pBl + gb);
        cpasync16(sb + 16384 + so1, pBl + gb + 16);
        cp_commit();
    };

    // ---- compute mapping: warp tile 64x32; wm in {0,1}, wn in {0..3}
    const int wm = wid & 1;
    const int wn = wid >> 1;
    const int aR  = wm * 64 + (lane & 15);
    const int aHi = lane >> 4;
    const int bR  = wn * 32 + (lane & 7) + ((lane >> 4) << 3);
    const int bHi = (lane >> 3) & 1;

    float acc[4][4][4];
#pragma unroll
    for (int i = 0; i < 4; i++)
#pragma unroll
        for (int j = 0; j < 4; j++)
#pragma unroll
            for (int p = 0; p < 4; p++) acc[i][j][p] = 0.f;

    issue(0); issue(1); issue(2);

#pragma unroll 1
    for (int kt = 0; kt < 32; kt++) {
        if (kt < 30)      cp_wait2();
        else if (kt == 30) cp_wait1();
        else               cp_wait0();
        __syncthreads();
        if (kt + 3 < 32) issue(kt + 3);   // overwrites stage consumed at kt-1

        const uint32_t sb = sbase + (kt & 3) * STAGE_BYTES;
#pragma unroll
        for (int ks = 0; ks < 2; ks++) {
            unsigned bh[2][4], bl[2][4];
#pragma unroll
            for (int np = 0; np < 2; np++) {
                int R  = bR + np * 16;
                int ch = 2 * ks + bHi;
                uint32_t bd = sb + 8192 + swzoff(R, ch);
                ldsm4(bh[np], bd);
                ldsm4(bl[np], bd + 8192);
            }
#pragma unroll
            for (int mb = 0; mb < 4; mb++) {
                unsigned ah[4];
                int R  = aR + mb * 16;
                int ch = 2 * ks + aHi;
                ldsm4(ah, sb + swzoff(R, ch));
#pragma unroll
                for (int nb = 0; nb < 4; nb++) {
                    mma16816(acc[mb][nb], ah, &bh[nb >> 1][(nb & 1) * 2]);
                    mma16816(acc[mb][nb], ah, &bl[nb >> 1][(nb & 1) * 2]);
                }
            }
        }
    }

    // ---- epilogue
    const int g  = lane >> 2;
    const int tt = lane & 3;
    const int mw = m0 + wm * 64;
    const int nw = n0 + wn * 32;

    if (stage == 0) {
        __half* Cf = (__half*)g_Cf4;
        const float sc = 1.f / 256.f;
#pragma unroll
        for (int mb = 0; mb < 4; mb++)
#pragma unroll
            for (int nb = 0; nb < 4; nb++) {
                const float* a = acc[mb][nb];
                size_t base = zoff + (size_t)(mw + mb * 16 + g) * 1024 + nw + nb * 8 + 2 * tt;
                *(unsigned*)&Cf[base]            = packh2(a[0] * sc, a[1] * sc);
                *(unsigned*)&Cf[base + 8 * 1024] = packh2(a[2] * sc, a[3] * sc);
            }
    } else {
        const float sc = SCALE / 256.f;
#pragma unroll
        for (int mb = 0; mb < 4; mb++)
#pragma unroll
            for (int nb = 0; nb < 4; nb++) {
                const float* a = acc[mb][nb];
                size_t base = zoff + (size_t)(mw + mb * 16 + g) * 1024 + nw + nb * 8 + 2 * tt;
                *(float2*)&g_X[base]            = make_float2(a[0] * sc, a[1] * sc);
                *(float2*)&g_X[base + 8 * 1024] = make_float2(a[2] * sc, a[3] * sc);
            }
    }
}

// ============================================================
// Kernel 6: output projection. Y[b,o,n] = b_out[o] + sum_c X[b,c,n]*w_out[o,c]
// ============================================================
__global__ __launch_bounds__(256) void proj_kernel(const float* __restrict__ wout,
                                                   const float* __restrict__ bout) {
    __shared__ float ws[32][64];
    const int b  = blockIdx.y;
    const int n  = blockIdx.x * 32 + (threadIdx.x & 31);
    const int og = threadIdx.x >> 5;
    const float* X = g_X + ((size_t)b << 22);

    float acc[4];
#pragma unroll
    for (int j = 0; j < 4; j++) acc[j] = bout[og * 4 + j];

    for (int c0 = 0; c0 < 4096; c0 += 64) {
        __syncthreads();
#pragma unroll
        for (int i = 0; i < 2; i++) {
            int idx = threadIdx.x + 256 * i;
            int o = idx >> 4, c4 = (idx & 15) << 2;
            *(float4*)&ws[o][c4] = *(const float4*)&wout[(size_t)o * 4096 + c0 + c4];
        }
        __syncthreads();
#pragma unroll 16
        for (int cl = 0; cl < 64; cl++) {
            float x = X[(size_t)(c0 + cl) * 1024 + n];
#pragma unroll
            for (int j = 0; j < 4; j++) acc[j] += ws[og * 4 + j][cl] * x;
        }
    }
#pragma unroll
    for (int j = 0; j < 4; j++)
        g_Y[((size_t)b * 32 + og * 4 + j) * 1024 + n] = acc[j];
}

// ============================================================
// Kernel 7: per-batch mean/var.
// ============================================================
__global__ __launch_bounds__(1024) void stats_kernel() {
    __shared__ float ss[32], ss2[32];
    const int b = blockIdx.x, t = threadIdx.x;
    const float* Y = g_Y + (size_t)b * 32768;
    float s = 0.f, s2 = 0.f;
#pragma unroll
    for (int k = 0; k < 32; k++) {
        float v = Y[t + 1024 * k];
        s += v; s2 += v * v;
    }
#pragma unroll
    for (int o = 16; o; o >>= 1) {
        s  += __shfl_xor_sync(0xffffffffu, s, o);
        s2 += __shfl_xor_sync(0xffffffffu, s2, o);
    }
    if ((t & 31) == 0) { ss[t >> 5] = s; ss2[t >> 5] = s2; }
    __syncthreads();
    if (t < 32) {
        s = ss[t]; s2 = ss2[t];
#pragma unroll
        for (int o = 16; o; o >>= 1) {
            s  += __shfl_xor_sync(0xffffffffu, s, o);
            s2 += __shfl_xor_sync(0xffffffffu, s2, o);
        }
        if (t == 0) {
            float mean = s * (1.f / 32768.f);
            g_stats[b]     = mean;
            g_stats[4 + b] = s2 * (1.f / 32768.f) - mean * mean;
        }
    }
}

// ============================================================
// Kernel 8: GroupNorm finalize -> d_out.
// ============================================================
__global__ void gn_kernel(const float* __restrict__ gamma,
                          const float* __restrict__ beta,
                          float* __restrict__ out) {
    int idx = blockIdx.x * 256 + threadIdx.x;
    int b = idx >> 15;
    int o = (idx >> 10) & 31;
    float mean = g_stats[b];
    float rstd = rsqrtf(g_stats[4 + b] + EPSGN);
    out[idx] = (g_Y[idx] - mean) * rstd * gamma[o] + beta[o];
}

// ============================================================
extern "C" void kernel_launch(void* const* d_in, const int* in_sizes, int n_in,
                              void* d_out, int out_size) {
    (void)in_sizes; (void)n_in; (void)out_size;
    const float* image = (const float*)d_in[0];
    const float* w_qkv = (const float*)d_in[1];
    const float* b_qkv = (const float*)d_in[2];
    const float* w_out = (const float*)d_in[3];
    const float* b_out = (const float*)d_in[4];
    const float* gamma = (const float*)d_in[5];
    const float* beta  = (const float*)d_in[6];
    float* out = (float*)d_out;

    cudaFuncSetAttribute(gemm_mma_kernel,
                         cudaFuncAttributeMaxDynamicSharedMemorySize, GEMM_SMEM);

    qkv_kernel<<<dim3(8, 192, 4), 256>>>(image, w_qkv, b_qkv);
    k_softmax_split_kernel<<<dim3(32, 16), 1024>>>();
    q_sum_kernel<<<dim3(32, 16), 256>>>();
    q_t_split_kernel<<<dim3(32, 32, 16), dim3(32, 8)>>>();
    gemm_mma_kernel<<<dim3(8, 8, 16), 256, GEMM_SMEM>>>(0);  // Cf = V * K^T
    gemm_mma_kernel<<<dim3(8, 8, 16), 256, GEMM_SMEM>>>(1);  // X  = Cf * QT^T
    proj_kernel<<<dim3(32, 4), 256>>>(w_out, b_out);
    stats_kernel<<<4, 1024>>>();
    gn_kernel<<<512, 256>>>(gamma, beta, out);
}

// round 9
// speedup vs baseline: 2.2441x; 1.0843x over previous
#include <cuda_runtime.h>
#include <cuda_fp16.h>
#include <math.h>
#include <stdint.h>

// ---------------- problem constants ----------------
#define NB    4
#define NC    32
#define NSP   1024
#define ND    1024
#define NBH   16
#define SCALE 0.17677669529663687f   // 1/sqrt(32)
#define EPSGN 1e-5f

// ---------------- scratch (device globals; allocation-free) ----------------
__device__ float g_Q  [NBH * ND * NSP];       // q natural [bh][d][n] fp32 (pre-softmax)
__device__ float g_K  [NBH * ND * NSP];       // k natural [bh][d][n] fp32 (pre-softmax)
__device__ float g_X  [NBH * ND * NSP];       // attention out [bh][e][n] fp32
__device__ float g_Y  [NB * NC * NSP];        // projection out, pre-GN
__device__ float g_stats[8];                  // mean[4], var[4]
__device__ float g_qinv[NBH * NSP];           // 256 / sum(exp(q)) per (z,n)

// f16 operand arrays, TILE-PACKED + PRE-SWIZZLED:
// layout: [z][tile(8)][kchunk(32)] blocks of 8192B; block = 128 rows x 64B,
// element (r, kk): byte r*64 + (((kk>>3)+(r>>1))&3)*16 + (kk&7)*2
#define HFN (NBH * ND * NSP / 8)
__device__ uint4 g_Vf4[HFN];                      // v  [e][n]            f16
__device__ uint4 g_Kh4[HFN]; __device__ uint4 g_Kl4[HFN];  // 256*k-softmax [d][n] hi/lo
__device__ uint4 g_Qh4[HFN]; __device__ uint4 g_Ql4[HFN];  // 256*q-softmax^T [n][d] hi/lo
__device__ uint4 g_Cf4[HFN];                      // ctx^T [e][d]         f16

// ---------------- small helpers ----------------
__device__ __forceinline__ uint32_t smem_u32(const void* p) {
    uint32_t a;
    asm("{ .reg .u64 t; cvta.to.shared.u64 t, %1; cvt.u32.u64 %0, t; }" : "=r"(a) : "l"(p));
    return a;
}
__device__ __forceinline__ unsigned packh2(float a, float b) {
    __half2 p = __floats2half2_rn(a, b);
    return *reinterpret_cast<unsigned*>(&p);
}
// byte offset of element (row, k) of matrix z in packed-swizzled layout
__device__ __forceinline__ size_t pkoff(int z, int row, int k) {
    size_t blk = (size_t)(z * 8 + (row >> 7)) * 32 + (k >> 5);
    int r = row & 127, kk = k & 31;
    return blk * 8192 +
           (uint32_t)(r * 64 + ((((kk >> 3) + (r >> 1)) & 3) << 4) + (kk & 7) * 2);
}
// in-smem 16B-chunk address within an 8KB region (same swizzle)
__device__ __forceinline__ uint32_t swzoff(int R, int ch) {
    return (uint32_t)(R * 64 + (((ch + (R >> 1)) & 3) << 4));
}
__device__ __forceinline__ void mbar_init(uint32_t a, uint32_t cnt) {
    asm volatile("mbarrier.init.shared.b64 [%0], %1;" :: "r"(a), "r"(cnt) : "memory");
}
__device__ __forceinline__ void mbar_expect_tx(uint32_t a, uint32_t tx) {
    asm volatile("mbarrier.arrive.expect_tx.shared.b64 _, [%0], %1;"
                 :: "r"(a), "r"(tx) : "memory");
}
__device__ __forceinline__ void mbar_wait(uint32_t a, uint32_t phase) {
    asm volatile(
        "{\n\t.reg .pred P;\n"
        "W%=:\n\t"
        "mbarrier.try_wait.parity.shared::cta.b64 P, [%0], %1;\n\t"
        "@!P bra W%=;\n\t}"
        :: "r"(a), "r"(phase) : "memory");
}
__device__ __forceinline__ void bulkcp(uint32_t sdst, const void* gsrc,
                                       uint32_t bytes, uint32_t mb) {
    asm volatile(
        "cp.async.bulk.shared::cta.global.mbarrier::complete_tx::bytes [%0], [%1], %2, [%3];"
        :: "r"(sdst), "l"(gsrc), "r"(bytes), "r"(mb) : "memory");
}
__device__ __forceinline__ void ldsm4(unsigned* r, uint32_t addr) {
    asm volatile("ldmatrix.sync.aligned.m8n8.x4.shared.b16 {%0,%1,%2,%3}, [%4];"
                 : "=r"(r[0]), "=r"(r[1]), "=r"(r[2]), "=r"(r[3]) : "r"(addr));
}
__device__ __forceinline__ void mma16816(float* c, const unsigned* a, const unsigned* b) {
    asm volatile(
        "mma.sync.aligned.m16n8k16.row.col.f32.f16.f16.f32 "
        "{%0,%1,%2,%3}, {%4,%5,%6,%7}, {%8,%9}, {%0,%1,%2,%3};"
        : "+f"(c[0]), "+f"(c[1]), "+f"(c[2]), "+f"(c[3])
        : "r"(a[0]), "r"(a[1]), "r"(a[2]), "r"(a[3]), "r"(b[0]), "r"(b[1]));
}

// ============================================================
// Kernel 1: QKV projection. q,k -> fp32 natural; v -> f16 packed.
// ============================================================
__global__ __launch_bounds__(256) void qkv_kernel(const float* __restrict__ img,
                                                  const float* __restrict__ w,
                                                  const float* __restrict__ bias) {
    __shared__ float xs[32][128];
    __shared__ float ws[64][32];
    __shared__ float bs[64];

    const int b  = blockIdx.z;
    const int o0 = blockIdx.y * 64;
    const int n0 = blockIdx.x * 128;
    const int t  = threadIdx.x;

#pragma unroll
    for (int i = 0; i < 4; i++) {
        int idx = t + 256 * i;
        int c = idx >> 5, c4 = (idx & 31) << 2;
        *(float4*)&xs[c][c4] = *(const float4*)&img[((size_t)b * 32 + c) * 1024 + n0 + c4];
    }
#pragma unroll
    for (int i = 0; i < 2; i++) {
        int idx = t + 256 * i;
        int o = idx >> 3, c4 = (idx & 7) << 2;
        *(float4*)&ws[o][c4] = *(const float4*)&w[(size_t)(o0 + o) * 32 + c4];
    }
    if (t < 64) bs[t] = bias[o0 + t];
    __syncthreads();

    const int tx = t & 31;
    const int oy = t >> 5;

    float acc[8][4];
#pragma unroll
    for (int r = 0; r < 8; r++) {
        float bv = bs[8 * oy + r];
#pragma unroll
        for (int i = 0; i < 4; i++) acc[r][i] = bv;
    }
#pragma unroll
    for (int c = 0; c < 32; c++) {
        float4 x = *(const float4*)&xs[c][4 * tx];
#pragma unroll
        for (int r = 0; r < 8; r++) {
            float wv = ws[8 * oy + r][c];
            acc[r][0] += wv * x.x; acc[r][1] += wv * x.y;
            acc[r][2] += wv * x.z; acc[r][3] += wv * x.w;
        }
    }

    const int nglob = n0 + 4 * tx;
#pragma unroll
    for (int r = 0; r < 8; r++) {
        int o     = o0 + 8 * oy + r;
        int which = o >> 12;
        int oc    = o & 4095;
        int h     = oc & 3;
        int cch   = oc >> 2;
        int zz    = b * 4 + h;
        if (which == 2) {
            uint2 hv;
            hv.x = packh2(acc[r][0], acc[r][1]);
            hv.y = packh2(acc[r][2], acc[r][3]);
            *(uint2*)((char*)g_Vf4 + pkoff(zz, cch, nglob)) = hv;   // 8B aligned (nglob%4==0)
        } else {
            float* dst = (which == 0) ? g_Q : g_K;
            *(float4*)&dst[((size_t)zz << 20) + (size_t)cch * 1024 + nglob] =
                make_float4(acc[r][0], acc[r][1], acc[r][2], acc[r][3]);
        }
    }
}

// ============================================================
// Kernel 2: k softmax over n (row-wise), x256, f16 hi/lo, packed layout.
// ============================================================
__global__ __launch_bounds__(1024) void k_softmax_split_kernel() {
    const int z    = blockIdx.y;
    const int lane = threadIdx.x & 31;
    const int w    = threadIdx.x >> 5;
    const int d    = blockIdx.x * 32 + w;
    const float* src = g_K + ((size_t)z << 20) + (size_t)d * 1024;

    float vals[32];
    float m = -3.402823466e38f;
#pragma unroll
    for (int j = 0; j < 32; j++) {
        vals[j] = src[j * 32 + lane];
        m = fmaxf(m, vals[j]);
    }
#pragma unroll
    for (int o = 16; o; o >>= 1) m = fmaxf(m, __shfl_xor_sync(0xffffffffu, m, o));
    float s = 0.f;
#pragma unroll
    for (int j = 0; j < 32; j++) { vals[j] = expf(vals[j] - m); s += vals[j]; }
#pragma unroll
    for (int o = 16; o; o >>= 1) s += __shfl_xor_sync(0xffffffffu, s, o);
    float inv = 256.f / s;

    char* KhB = (char*)g_Kh4;
    char* KlB = (char*)g_Kl4;
#pragma unroll
    for (int j = 0; j < 32; j++) {
        float v = vals[j] * inv;
        __half h = __float2half_rn(v);
        size_t off = pkoff(z, d, j * 32 + lane);
        *(__half*)(KhB + off) = h;
        *(__half*)(KlB + off) = __float2half_rn(v - __half2float(h));
    }
}

// ============================================================
// Kernel 3: q denominator: g_qinv[z][n] = 256 / sum_d exp(q[d][n]).
// ============================================================
__global__ __launch_bounds__(256) void q_sum_kernel() {
    __shared__ float red[8][32];
    const int z  = blockIdx.y;
    const int nl = threadIdx.x & 31;
    const int dg = threadIdx.x >> 5;
    const int n  = blockIdx.x * 32 + nl;
    const float* src = g_Q + ((size_t)z << 20) + n;

    float s = 0.f;
#pragma unroll 8
    for (int d = dg * 128; d < dg * 128 + 128; d++) s += expf(src[(size_t)d * 1024]);
    red[dg][nl] = s;
    __syncthreads();
    if (dg == 0) {
        float tot = 0.f;
#pragma unroll
        for (int r = 0; r < 8; r++) tot += red[r][nl];
        g_qinv[z * 1024 + n] = 256.f / tot;
    }
}

// ============================================================
// Kernel 4: q softmax-apply (x256) + transpose + f16 split, packed layout.
// ============================================================
__global__ void q_t_split_kernel() {
    __shared__ float s[32][33];
    const int z  = blockIdx.z;
    const int d0 = blockIdx.y * 32;
    const int n0 = blockIdx.x * 32;
    const int tx = threadIdx.x, ty = threadIdx.y;
    const float* src = g_Q + ((size_t)z << 20);
    const float inv = g_qinv[z * 1024 + n0 + tx];

#pragma unroll
    for (int i = 0; i < 4; i++) {
        int r = ty + 8 * i;
        s[r][tx] = expf(src[(size_t)(d0 + r) * 1024 + n0 + tx]) * inv;
    }
    __syncthreads();

    char* QhB = (char*)g_Qh4;
    char* QlB = (char*)g_Ql4;
#pragma unroll
    for (int i = 0; i < 4; i++) {
        int nl = ty + 8 * i;
        float v = s[tx][nl];
        __half h = __float2half_rn(v);
        size_t off = pkoff(z, n0 + nl, d0 + tx);
        *(__half*)(QhB + off) = h;
        *(__half*)(QlB + off) = __float2half_rn(v - __half2float(h));
    }
}

// ============================================================
// Kernel 5: f16 2-pass split TN GEMM, bulk-TMA loads + mma.sync.
//   D[m,n'] = sum_k A[m,k]*(Bh[n',k]+Bl[n',k])
// stage 0: A=Vf,  B={Kh,Kl} (256x) -> Cf packed, scale 1/256
// stage 1: A=Cf,  B={Qh,Ql} (256x) -> X [e][n] fp32, scale SCALE/256
// 128x128 tile, K chunk 32, 4-stage mbarrier ring; loads are 3
// cp.async.bulk (24KB) issued by thread 0 per chunk.
// grid (8, 8, 16), block 256.
// ============================================================
#define STAGE_BYTES 24576
#define NSTAGE 4
#define GEMM_SMEM (NSTAGE * STAGE_BYTES + 32)

__global__ __launch_bounds__(256, 2) void gemm_mma_kernel(int stage) {
    extern __shared__ char smem[];
    const uint32_t sbase = smem_u32(smem);
    const uint32_t mbar  = sbase + NSTAGE * STAGE_BYTES;
    const int t    = threadIdx.x;
    const int lane = t & 31;
    const int wid  = t >> 5;

    const char *A, *Bh, *Bl;
    if (stage == 0) {
        A  = (const char*)g_Vf4;
        Bh = (const char*)g_Kh4; Bl = (const char*)g_Kl4;
    } else {
        A  = (const char*)g_Cf4;
        Bh = (const char*)g_Qh4; Bl = (const char*)g_Ql4;
    }
    const int z  = blockIdx.z;
    const int mt = blockIdx.y;
    const int nt = blockIdx.x;
    const char* gA  = A  + (size_t)(z * 8 + mt) * 32 * 8192;
    const char* gBh = Bh + (size_t)(z * 8 + nt) * 32 * 8192;
    const char* gBl = Bl + (size_t)(z * 8 + nt) * 32 * 8192;

    if (t == 0) {
#pragma unroll
        for (int s = 0; s < NSTAGE; s++) mbar_init(mbar + 8 * s, 1);
        asm volatile("fence.proxy.async.shared::cta;" ::: "memory");
    }
    __syncthreads();

    auto issue = [&](int kt) {
        const uint32_t mb = mbar + 8 * (kt & 3);
        const uint32_t sb = sbase + (kt & 3) * STAGE_BYTES;
        mbar_expect_tx(mb, STAGE_BYTES);
        bulkcp(sb,         gA  + (size_t)kt * 8192, 8192, mb);
        bulkcp(sb + 8192,  gBh + (size_t)kt * 8192, 8192, mb);
        bulkcp(sb + 16384, gBl + (size_t)kt * 8192, 8192, mb);
    };
    if (t == 0) { issue(0); issue(1); issue(2); }

    // compute mapping: warp tile 64x32; wm in {0,1}, wn in {0..3}
    const int wm = wid & 1;
    const int wn = wid >> 1;
    const int aR  = wm * 64 + (lane & 15);
    const int aHi = lane >> 4;
    const int bR  = wn * 32 + (lane & 7) + ((lane >> 4) << 3);
    const int bHi = (lane >> 3) & 1;

    float acc[4][4][4];
#pragma unroll
    for (int i = 0; i < 4; i++)
#pragma unroll
        for (int j = 0; j < 4; j++)
#pragma unroll
            for (int p = 0; p < 4; p++) acc[i][j][p] = 0.f;

#pragma unroll 1
    for (int kt = 0; kt < 32; kt++) {
        mbar_wait(mbar + 8 * (kt & 3), (kt >> 2) & 1);
        __syncthreads();                 // all warps done reading stage (kt-1)
        if (t == 0 && kt + 3 < 32) issue(kt + 3);   // overwrites stage (kt-1)&3

        const uint32_t sb = sbase + (kt & 3) * STAGE_BYTES;
#pragma unroll
        for (int ks = 0; ks < 2; ks++) {
            unsigned bh[2][4], bl[2][4];
#pragma unroll
            for (int np = 0; np < 2; np++) {
                int R  = bR + np * 16;
                int ch = 2 * ks + bHi;
                uint32_t bd = sb + 8192 + swzoff(R, ch);
                ldsm4(bh[np], bd);
                ldsm4(bl[np], bd + 8192);
            }
#pragma unroll
            for (int mb = 0; mb < 4; mb++) {
                unsigned ah[4];
                int R  = aR + mb * 16;
                int ch = 2 * ks + aHi;
                ldsm4(ah, sb + swzoff(R, ch));
#pragma unroll
                for (int nb = 0; nb < 4; nb++) {
                    mma16816(acc[mb][nb], ah, &bh[nb >> 1][(nb & 1) * 2]);
                    mma16816(acc[mb][nb], ah, &bl[nb >> 1][(nb & 1) * 2]);
                }
            }
        }
    }

    // ---- epilogue
    const int g  = lane >> 2;
    const int tt = lane & 3;
    const int mw = mt * 128 + wm * 64;
    const int nw = nt * 128 + wn * 32;

    if (stage == 0) {
        char* Cf = (char*)g_Cf4;
        const float sc = 1.f / 256.f;
#pragma unroll
        for (int mb = 0; mb < 4; mb++)
#pragma unroll
            for (int nb = 0; nb < 4; nb++) {
                const float* a = acc[mb][nb];
                int m = mw + mb * 16 + g;
                int k = nw + nb * 8 + 2 * tt;
                *(unsigned*)(Cf + pkoff(z, m,     k)) = packh2(a[0] * sc, a[1] * sc);
                *(unsigned*)(Cf + pkoff(z, m + 8, k)) = packh2(a[2] * sc, a[3] * sc);
            }
    } else {
        const float sc = SCALE / 256.f;
        const size_t zoff = (size_t)z << 20;
#pragma unroll
        for (int mb = 0; mb < 4; mb++)
#pragma unroll
            for (int nb = 0; nb < 4; nb++) {
                const float* a = acc[mb][nb];
                size_t base = zoff + (size_t)(mw + mb * 16 + g) * 1024 + nw + nb * 8 + 2 * tt;
                *(float2*)&g_X[base]            = make_float2(a[0] * sc, a[1] * sc);
                *(float2*)&g_X[base + 8 * 1024] = make_float2(a[2] * sc, a[3] * sc);
            }
    }
}

// ============================================================
// Kernel 6: output projection. Y[b,o,n] = b_out[o] + sum_c X[b,c,n]*w_out[o,c]
// ============================================================
__global__ __launch_bounds__(256) void proj_kernel(const float* __restrict__ wout,
                                                   const float* __restrict__ bout) {
    __shared__ float ws[32][64];
    const int b  = blockIdx.y;
    const int n  = blockIdx.x * 32 + (threadIdx.x & 31);
    const int og = threadIdx.x >> 5;
    const float* X = g_X + ((size_t)b << 22);

    float acc[4];
#pragma unroll
    for (int j = 0; j < 4; j++) acc[j] = bout[og * 4 + j];

    for (int c0 = 0; c0 < 4096; c0 += 64) {
        __syncthreads();
#pragma unroll
        for (int i = 0; i < 2; i++) {
            int idx = threadIdx.x + 256 * i;
            int o = idx >> 4, c4 = (idx & 15) << 2;
            *(float4*)&ws[o][c4] = *(const float4*)&wout[(size_t)o * 4096 + c0 + c4];
        }
        __syncthreads();
#pragma unroll 16
        for (int cl = 0; cl < 64; cl++) {
            float x = X[(size_t)(c0 + cl) * 1024 + n];
#pragma unroll
            for (int j = 0; j < 4; j++) acc[j] += ws[og * 4 + j][cl] * x;
        }
    }
#pragma unroll
    for (int j = 0; j < 4; j++)
        g_Y[((size_t)b * 32 + og * 4 + j) * 1024 + n] = acc[j];
}

// ============================================================
// Kernel 7: per-batch mean/var.
// ============================================================
__global__ __launch_bounds__(1024) void stats_kernel() {
    __shared__ float ss[32], ss2[32];
    const int b = blockIdx.x, t = threadIdx.x;
    const float* Y = g_Y + (size_t)b * 32768;
    float s = 0.f, s2 = 0.f;
#pragma unroll
    for (int k = 0; k < 32; k++) {
        float v = Y[t + 1024 * k];
        s += v; s2 += v * v;
    }
#pragma unroll
    for (int o = 16; o; o >>= 1) {
        s  += __shfl_xor_sync(0xffffffffu, s, o);
        s2 += __shfl_xor_sync(0xffffffffu, s2, o);
    }
    if ((t & 31) == 0) { ss[t >> 5] = s; ss2[t >> 5] = s2; }
    __syncthreads();
    if (t < 32) {
        s = ss[t]; s2 = ss2[t];
#pragma unroll
        for (int o = 16; o; o >>= 1) {
            s  += __shfl_xor_sync(0xffffffffu, s, o);
            s2 += __shfl_xor_sync(0xffffffffu, s2, o);
        }
        if (t == 0) {
            float mean = s * (1.f / 32768.f);
            g_stats[b]     = mean;
            g_stats[4 + b] = s2 * (1.f / 32768.f) - mean * mean;
        }
    }
}

// ============================================================
// Kernel 8: GroupNorm finalize -> d_out.
// ============================================================
__global__ void gn_kernel(const float* __restrict__ gamma,
                          const float* __restrict__ beta,
                          float* __restrict__ out) {
    int idx = blockIdx.x * 256 + threadIdx.x;
    int b = idx >> 15;
    int o = (idx >> 10) & 31;
    float mean = g_stats[b];
    float rstd = rsqrtf(g_stats[4 + b] + EPSGN);
    out[idx] = (g_Y[idx] - mean) * rstd * gamma[o] + beta[o];
}

// ============================================================
extern "C" void kernel_launch(void* const* d_in, const int* in_sizes, int n_in,
                              void* d_out, int out_size) {
    (void)in_sizes; (void)n_in; (void)out_size;
    const float* image = (const float*)d_in[0];
    const float* w_qkv = (const float*)d_in[1];
    const float* b_qkv = (const float*)d_in[2];
    const float* w_out = (const float*)d_in[3];
    const float* b_out = (const float*)d_in[4];
    const float* gamma = (const float*)d_in[5];
    const float* beta  = (const float*)d_in[6];
    float* out = (float*)d_out;

    cudaFuncSetAttribute(gemm_mma_kernel,
                         cudaFuncAttributeMaxDynamicSharedMemorySize, GEMM_SMEM);

    qkv_kernel<<<dim3(8, 192, 4), 256>>>(image, w_qkv, b_qkv);
    k_softmax_split_kernel<<<dim3(32, 16), 1024>>>();
    q_sum_kernel<<<dim3(32, 16), 256>>>();
    q_t_split_kernel<<<dim3(32, 32, 16), dim3(32, 8)>>>();
    gemm_mma_kernel<<<dim3(8, 8, 16), 256, GEMM_SMEM>>>(0);  // Cf = V * K^T
    gemm_mma_kernel<<<dim3(8, 8, 16), 256, GEMM_SMEM>>>(1);  // X  = Cf * QT^T
    proj_kernel<<<dim3(32, 4), 256>>>(w_out, b_out);
    stats_kernel<<<4, 1024>>>();
    gn_kernel<<<512, 256>>>(gamma, beta, out);
}

// round 10
// speedup vs baseline: 2.5845x; 1.1517x over previous
#include <cuda_runtime.h>
#include <cuda_fp16.h>
#include <math.h>
#include <stdint.h>

// ---------------- problem constants ----------------
#define NB    4
#define NC    32
#define NSP   1024
#define ND    1024
#define NBH   16
#define SCALE 0.17677669529663687f   // 1/sqrt(32)
#define EPSGN 1e-5f

// ---------------- scratch (device globals; allocation-free) ----------------
__device__ float g_Q  [NBH * ND * NSP];       // q natural [bh][d][n] fp32 (pre-softmax)
__device__ float g_K  [NBH * ND * NSP];       // k natural [bh][d][n] fp32 (pre-softmax)
__device__ float g_X  [NBH * ND * NSP];       // attention out [bh][e][n] fp32
__device__ float g_Y  [NB * NC * NSP];        // projection out, pre-GN
__device__ float g_stats[8];                  // mean[4], var[4]
__device__ float g_qinv[NBH * NSP];           // 256 / sum(exp(q)) per (z,n)

// f16 operand arrays, TILE-PACKED + PRE-SWIZZLED:
// layout: [z][tile(8)][kchunk(32)] blocks of 8192B; block = 128 rows x 64B,
// element (r, kk): byte r*64 + (((kk>>3)+(r>>1))&3)*16 + (kk&7)*2
#define HFN (NBH * ND * NSP / 8)
__device__ uint4 g_Vf4[HFN];   // v  [e][n]             f16
__device__ uint4 g_Kf4[HFN];   // 256*k-softmax [d][n]  f16
__device__ uint4 g_Qf4[HFN];   // 256*q-softmax^T [n][d] f16
__device__ uint4 g_Cf4[HFN];   // ctx^T [e][d]          f16

// ---------------- small helpers ----------------
__device__ __forceinline__ uint32_t smem_u32(const void* p) {
    uint32_t a;
    asm("{ .reg .u64 t; cvta.to.shared.u64 t, %1; cvt.u32.u64 %0, t; }" : "=r"(a) : "l"(p));
    return a;
}
__device__ __forceinline__ unsigned packh2(float a, float b) {
    __half2 p = __floats2half2_rn(a, b);
    return *reinterpret_cast<unsigned*>(&p);
}
// byte offset of element (row, k) of matrix z in packed-swizzled layout
__device__ __forceinline__ size_t pkoff(int z, int row, int k) {
    size_t blk = (size_t)(z * 8 + (row >> 7)) * 32 + (k >> 5);
    int r = row & 127, kk = k & 31;
    return blk * 8192 +
           (uint32_t)(r * 64 + ((((kk >> 3) + (r >> 1)) & 3) << 4) + (kk & 7) * 2);
}
// in-smem 16B-chunk address within an 8KB region (same swizzle)
__device__ __forceinline__ uint32_t swzoff(int R, int ch) {
    return (uint32_t)(R * 64 + (((ch + (R >> 1)) & 3) << 4));
}
__device__ __forceinline__ void mbar_init(uint32_t a, uint32_t cnt) {
    asm volatile("mbarrier.init.shared.b64 [%0], %1;" :: "r"(a), "r"(cnt) : "memory");
}
__device__ __forceinline__ void mbar_expect_tx(uint32_t a, uint32_t tx) {
    asm volatile("mbarrier.arrive.expect_tx.shared.b64 _, [%0], %1;"
                 :: "r"(a), "r"(tx) : "memory");
}
__device__ __forceinline__ void mbar_wait(uint32_t a, uint32_t phase) {
    asm volatile(
        "{\n\t.reg .pred P;\n"
        "W%=:\n\t"
        "mbarrier.try_wait.parity.shared::cta.b64 P, [%0], %1;\n\t"
        "@!P bra W%=;\n\t}"
        :: "r"(a), "r"(phase) : "memory");
}
__device__ __forceinline__ void bulkcp(uint32_t sdst, const void* gsrc,
                                       uint32_t bytes, uint32_t mb) {
    asm volatile(
        "cp.async.bulk.shared::cta.global.mbarrier::complete_tx::bytes [%0], [%1], %2, [%3];"
        :: "r"(sdst), "l"(gsrc), "r"(bytes), "r"(mb) : "memory");
}
__device__ __forceinline__ void ldsm4(unsigned* r, uint32_t addr) {
    asm volatile("ldmatrix.sync.aligned.m8n8.x4.shared.b16 {%0,%1,%2,%3}, [%4];"
                 : "=r"(r[0]), "=r"(r[1]), "=r"(r[2]), "=r"(r[3]) : "r"(addr));
}
__device__ __forceinline__ void mma16816(float* c, const unsigned* a, const unsigned* b) {
    asm volatile(
        "mma.sync.aligned.m16n8k16.row.col.f32.f16.f16.f32 "
        "{%0,%1,%2,%3}, {%4,%5,%6,%7}, {%8,%9}, {%0,%1,%2,%3};"
        : "+f"(c[0]), "+f"(c[1]), "+f"(c[2]), "+f"(c[3])
        : "r"(a[0]), "r"(a[1]), "r"(a[2]), "r"(a[3]), "r"(b[0]), "r"(b[1]));
}

// ============================================================
// Kernel 1: QKV projection. q,k -> fp32 natural; v -> f16 packed.
// ============================================================
__global__ __launch_bounds__(256) void qkv_kernel(const float* __restrict__ img,
                                                  const float* __restrict__ w,
                                                  const float* __restrict__ bias) {
    __shared__ float xs[32][128];
    __shared__ float ws[64][32];
    __shared__ float bs[64];

    const int b  = blockIdx.z;
    const int o0 = blockIdx.y * 64;
    const int n0 = blockIdx.x * 128;
    const int t  = threadIdx.x;

#pragma unroll
    for (int i = 0; i < 4; i++) {
        int idx = t + 256 * i;
        int c = idx >> 5, c4 = (idx & 31) << 2;
        *(float4*)&xs[c][c4] = *(const float4*)&img[((size_t)b * 32 + c) * 1024 + n0 + c4];
    }
#pragma unroll
    for (int i = 0; i < 2; i++) {
        int idx = t + 256 * i;
        int o = idx >> 3, c4 = (idx & 7) << 2;
        *(float4*)&ws[o][c4] = *(const float4*)&w[(size_t)(o0 + o) * 32 + c4];
    }
    if (t < 64) bs[t] = bias[o0 + t];
    __syncthreads();

    const int tx = t & 31;
    const int oy = t >> 5;

    float acc[8][4];
#pragma unroll
    for (int r = 0; r < 8; r++) {
        float bv = bs[8 * oy + r];
#pragma unroll
        for (int i = 0; i < 4; i++) acc[r][i] = bv;
    }
#pragma unroll
    for (int c = 0; c < 32; c++) {
        float4 x = *(const float4*)&xs[c][4 * tx];
#pragma unroll
        for (int r = 0; r < 8; r++) {
            float wv = ws[8 * oy + r][c];
            acc[r][0] += wv * x.x; acc[r][1] += wv * x.y;
            acc[r][2] += wv * x.z; acc[r][3] += wv * x.w;
        }
    }

    const int nglob = n0 + 4 * tx;
#pragma unroll
    for (int r = 0; r < 8; r++) {
        int o     = o0 + 8 * oy + r;
        int which = o >> 12;
        int oc    = o & 4095;
        int h     = oc & 3;
        int cch   = oc >> 2;
        int zz    = b * 4 + h;
        if (which == 2) {
            uint2 hv;
            hv.x = packh2(acc[r][0], acc[r][1]);
            hv.y = packh2(acc[r][2], acc[r][3]);
            *(uint2*)((char*)g_Vf4 + pkoff(zz, cch, nglob)) = hv;   // 8B aligned (nglob%4==0)
        } else {
            float* dst = (which == 0) ? g_Q : g_K;
            *(float4*)&dst[((size_t)zz << 20) + (size_t)cch * 1024 + nglob] =
                make_float4(acc[r][0], acc[r][1], acc[r][2], acc[r][3]);
        }
    }
}

// ============================================================
// Kernel 2: k softmax over n (row-wise), x256, f16, packed layout.
// ============================================================
__global__ __launch_bounds__(1024) void k_softmax_kernel() {
    const int z    = blockIdx.y;
    const int lane = threadIdx.x & 31;
    const int w    = threadIdx.x >> 5;
    const int d    = blockIdx.x * 32 + w;
    const float* src = g_K + ((size_t)z << 20) + (size_t)d * 1024;

    float vals[32];
    float m = -3.402823466e38f;
#pragma unroll
    for (int j = 0; j < 32; j++) {
        vals[j] = src[j * 32 + lane];
        m = fmaxf(m, vals[j]);
    }
#pragma unroll
    for (int o = 16; o; o >>= 1) m = fmaxf(m, __shfl_xor_sync(0xffffffffu, m, o));
    float s = 0.f;
#pragma unroll
    for (int j = 0; j < 32; j++) { vals[j] = expf(vals[j] - m); s += vals[j]; }
#pragma unroll
    for (int o = 16; o; o >>= 1) s += __shfl_xor_sync(0xffffffffu, s, o);
    float inv = 256.f / s;

    char* KfB = (char*)g_Kf4;
#pragma unroll
    for (int j = 0; j < 32; j++)
        *(__half*)(KfB + pkoff(z, d, j * 32 + lane)) = __float2half_rn(vals[j] * inv);
}

// ============================================================
// Kernel 3: q denominator: g_qinv[z][n] = 256 / sum_d exp(q[d][n]).
// ============================================================
__global__ __launch_bounds__(256) void q_sum_kernel() {
    __shared__ float red[8][32];
    const int z  = blockIdx.y;
    const int nl = threadIdx.x & 31;
    const int dg = threadIdx.x >> 5;
    const int n  = blockIdx.x * 32 + nl;
    const float* src = g_Q + ((size_t)z << 20) + n;

    float s = 0.f;
#pragma unroll 8
    for (int d = dg * 128; d < dg * 128 + 128; d++) s += expf(src[(size_t)d * 1024]);
    red[dg][nl] = s;
    __syncthreads();
    if (dg == 0) {
        float tot = 0.f;
#pragma unroll
        for (int r = 0; r < 8; r++) tot += red[r][nl];
        g_qinv[z * 1024 + n] = 256.f / tot;
    }
}

// ============================================================
// Kernel 4: q softmax-apply (x256) + transpose -> f16 packed qT[n][d].
// ============================================================
__global__ void q_t_kernel() {
    __shared__ float s[32][33];
    const int z  = blockIdx.z;
    const int d0 = blockIdx.y * 32;
    const int n0 = blockIdx.x * 32;
    const int tx = threadIdx.x, ty = threadIdx.y;
    const float* src = g_Q + ((size_t)z << 20);
    const float inv = g_qinv[z * 1024 + n0 + tx];

#pragma unroll
    for (int i = 0; i < 4; i++) {
        int r = ty + 8 * i;
        s[r][tx] = expf(src[(size_t)(d0 + r) * 1024 + n0 + tx]) * inv;
    }
    __syncthreads();

    char* QfB = (char*)g_Qf4;
#pragma unroll
    for (int i = 0; i < 4; i++) {
        int nl = ty + 8 * i;
        *(__half*)(QfB + pkoff(z, n0 + nl, d0 + tx)) = __float2half_rn(s[tx][nl]);
    }
}

// ============================================================
// Kernel 5: single-pass f16 TN GEMM, bulk-TMA loads + mma.sync.
//   D[m,n'] = sum_k A[m,k]*B[n',k]
// stage 0: A=Vf, B=Kf (256x) -> Cf packed, scale 1/256
// stage 1: A=Cf, B=Qf (256x) -> X [e][n] fp32, scale SCALE/256
// 128x128 tile, K chunk 32, 4-stage mbarrier ring; loads are 2
// cp.async.bulk (16KB) issued by thread 0 per chunk.
// grid (8, 8, 16), block 256, 2 CTAs/SM.
// ============================================================
#define STAGE_BYTES 16384
#define NSTAGE 4
#define GEMM_SMEM (NSTAGE * STAGE_BYTES + 32)

__global__ __launch_bounds__(256, 2) void gemm_mma_kernel(int stage) {
    extern __shared__ char smem[];
    const uint32_t sbase = smem_u32(smem);
    const uint32_t mbar  = sbase + NSTAGE * STAGE_BYTES;
    const int t    = threadIdx.x;
    const int lane = t & 31;
    const int wid  = t >> 5;

    const char *A, *B;
    if (stage == 0) { A = (const char*)g_Vf4; B = (const char*)g_Kf4; }
    else            { A = (const char*)g_Cf4; B = (const char*)g_Qf4; }
    const int z  = blockIdx.z;
    const int mt = blockIdx.y;
    const int nt = blockIdx.x;
    const char* gA = A + (size_t)(z * 8 + mt) * 32 * 8192;
    const char* gB = B + (size_t)(z * 8 + nt) * 32 * 8192;

    if (t == 0) {
#pragma unroll
        for (int s = 0; s < NSTAGE; s++) mbar_init(mbar + 8 * s, 1);
        asm volatile("fence.proxy.async.shared::cta;" ::: "memory");
    }
    __syncthreads();

    auto issue = [&](int kt) {
        const uint32_t mb = mbar + 8 * (kt & 3);
        const uint32_t sb = sbase + (kt & 3) * STAGE_BYTES;
        mbar_expect_tx(mb, STAGE_BYTES);
        bulkcp(sb,        gA + (size_t)kt * 8192, 8192, mb);
        bulkcp(sb + 8192, gB + (size_t)kt * 8192, 8192, mb);
    };
    if (t == 0) { issue(0); issue(1); issue(2); }

    // compute mapping: warp tile 64x32; wm in {0,1}, wn in {0..3}
    const int wm = wid & 1;
    const int wn = wid >> 1;
    const int aR  = wm * 64 + (lane & 15);
    const int aHi = lane >> 4;
    const int bR  = wn * 32 + (lane & 7) + ((lane >> 4) << 3);
    const int bHi = (lane >> 3) & 1;

    float acc[4][4][4];
#pragma unroll
    for (int i = 0; i < 4; i++)
#pragma unroll
        for (int j = 0; j < 4; j++)
#pragma unroll
            for (int p = 0; p < 4; p++) acc[i][j][p] = 0.f;

#pragma unroll 1
    for (int kt = 0; kt < 32; kt++) {
        mbar_wait(mbar + 8 * (kt & 3), (kt >> 2) & 1);
        __syncthreads();                 // all warps done reading stage (kt-1)
        if (t == 0 && kt + 3 < 32) issue(kt + 3);   // overwrites stage (kt-1)&3

        const uint32_t sb = sbase + (kt & 3) * STAGE_BYTES;
#pragma unroll
        for (int ks = 0; ks < 2; ks++) {
            unsigned bf[2][4];
#pragma unroll
            for (int np = 0; np < 2; np++) {
                int R  = bR + np * 16;
                int ch = 2 * ks + bHi;
                ldsm4(bf[np], sb + 8192 + swzoff(R, ch));
            }
#pragma unroll
            for (int mb = 0; mb < 4; mb++) {
                unsigned ah[4];
                int R  = aR + mb * 16;
                int ch = 2 * ks + aHi;
                ldsm4(ah, sb + swzoff(R, ch));
#pragma unroll
                for (int nb = 0; nb < 4; nb++)
                    mma16816(acc[mb][nb], ah, &bf[nb >> 1][(nb & 1) * 2]);
            }
        }
    }

    // ---- epilogue
    const int g  = lane >> 2;
    const int tt = lane & 3;
    const int mw = mt * 128 + wm * 64;
    const int nw = nt * 128 + wn * 32;

    if (stage == 0) {
        char* Cf = (char*)g_Cf4;
        const float sc = 1.f / 256.f;
#pragma unroll
        for (int mb = 0; mb < 4; mb++)
#pragma unroll
            for (int nb = 0; nb < 4; nb++) {
                const float* a = acc[mb][nb];
                int m = mw + mb * 16 + g;
                int k = nw + nb * 8 + 2 * tt;
                *(unsigned*)(Cf + pkoff(z, m,     k)) = packh2(a[0] * sc, a[1] * sc);
                *(unsigned*)(Cf + pkoff(z, m + 8, k)) = packh2(a[2] * sc, a[3] * sc);
            }
    } else {
        const float sc = SCALE / 256.f;
        const size_t zoff = (size_t)z << 20;
#pragma unroll
        for (int mb = 0; mb < 4; mb++)
#pragma unroll
            for (int nb = 0; nb < 4; nb++) {
                const float* a = acc[mb][nb];
                size_t base = zoff + (size_t)(mw + mb * 16 + g) * 1024 + nw + nb * 8 + 2 * tt;
                *(float2*)&g_X[base]            = make_float2(a[0] * sc, a[1] * sc);
                *(float2*)&g_X[base + 8 * 1024] = make_float2(a[2] * sc, a[3] * sc);
            }
    }
}

// ============================================================
// Kernel 6: output projection. Y[b,o,n] = b_out[o] + sum_c X[b,c,n]*w_out[o,c]
// ============================================================
__global__ __launch_bounds__(256) void proj_kernel(const float* __restrict__ wout,
                                                   const float* __restrict__ bout) {
    __shared__ float ws[32][64];
    const int b  = blockIdx.y;
    const int n  = blockIdx.x * 32 + (threadIdx.x & 31);
    const int og = threadIdx.x >> 5;
    const float* X = g_X + ((size_t)b << 22);

    float acc[4];
#pragma unroll
    for (int j = 0; j < 4; j++) acc[j] = bout[og * 4 + j];

    for (int c0 = 0; c0 < 4096; c0 += 64) {
        __syncthreads();
#pragma unroll
        for (int i = 0; i < 2; i++) {
            int idx = threadIdx.x + 256 * i;
            int o = idx >> 4, c4 = (idx & 15) << 2;
            *(float4*)&ws[o][c4] = *(const float4*)&wout[(size_t)o * 4096 + c0 + c4];
        }
        __syncthreads();
#pragma unroll 16
        for (int cl = 0; cl < 64; cl++) {
            float x = X[(size_t)(c0 + cl) * 1024 + n];
#pragma unroll
            for (int j = 0; j < 4; j++) acc[j] += ws[og * 4 + j][cl] * x;
        }
    }
#pragma unroll
    for (int j = 0; j < 4; j++)
        g_Y[((size_t)b * 32 + og * 4 + j) * 1024 + n] = acc[j];
}

// ============================================================
// Kernel 7: per-batch mean/var.
// ============================================================
__global__ __launch_bounds__(1024) void stats_kernel() {
    __shared__ float ss[32], ss2[32];
    const int b = blockIdx.x, t = threadIdx.x;
    const float* Y = g_Y + (size_t)b * 32768;
    float s = 0.f, s2 = 0.f;
#pragma unroll
    for (int k = 0; k < 32; k++) {
        float v = Y[t + 1024 * k];
        s += v; s2 += v * v;
    }
#pragma unroll
    for (int o = 16; o; o >>= 1) {
        s  += __shfl_xor_sync(0xffffffffu, s, o);
        s2 += __shfl_xor_sync(0xffffffffu, s2, o);
    }
    if ((t & 31) == 0) { ss[t >> 5] = s; ss2[t >> 5] = s2; }
    __syncthreads();
    if (t < 32) {
        s = ss[t]; s2 = ss2[t];
#pragma unroll
        for (int o = 16; o; o >>= 1) {
            s  += __shfl_xor_sync(0xffffffffu, s, o);
            s2 += __shfl_xor_sync(0xffffffffu, s2, o);
        }
        if (t == 0) {
            float mean = s * (1.f / 32768.f);
            g_stats[b]     = mean;
            g_stats[4 + b] = s2 * (1.f / 32768.f) - mean * mean;
        }
    }
}

// ============================================================
// Kernel 8: GroupNorm finalize -> d_out.
// ============================================================
__global__ void gn_kernel(const float* __restrict__ gamma,
                          const float* __restrict__ beta,
                          float* __restrict__ out) {
    int idx = blockIdx.x * 256 + threadIdx.x;
    int b = idx >> 15;
    int o = (idx >> 10) & 31;
    float mean = g_stats[b];
    float rstd = rsqrtf(g_stats[4 + b] + EPSGN);
    out[idx] = (g_Y[idx] - mean) * rstd * gamma[o] + beta[o];
}

// ============================================================
extern "C" void kernel_launch(void* const* d_in, const int* in_sizes, int n_in,
                              void* d_out, int out_size) {
    (void)in_sizes; (void)n_in; (void)out_size;
    const float* image = (const float*)d_in[0];
    const float* w_qkv = (const float*)d_in[1];
    const float* b_qkv = (const float*)d_in[2];
    const float* w_out = (const float*)d_in[3];
    const float* b_out = (const float*)d_in[4];
    const float* gamma = (const float*)d_in[5];
    const float* beta  = (const float*)d_in[6];
    float* out = (float*)d_out;

    cudaFuncSetAttribute(gemm_mma_kernel,
                         cudaFuncAttributeMaxDynamicSharedMemorySize, GEMM_SMEM);

    qkv_kernel<<<dim3(8, 192, 4), 256>>>(image, w_qkv, b_qkv);
    k_softmax_kernel<<<dim3(32, 16), 1024>>>();
    q_sum_kernel<<<dim3(32, 16), 256>>>();
    q_t_kernel<<<dim3(32, 32, 16), dim3(32, 8)>>>();
    gemm_mma_kernel<<<dim3(8, 8, 16), 256, GEMM_SMEM>>>(0);  // Cf = V * K^T
    gemm_mma_kernel<<<dim3(8, 8, 16), 256, GEMM_SMEM>>>(1);  // X  = Cf * QT^T
    proj_kernel<<<dim3(32, 4), 256>>>(w_out, b_out);
    stats_kernel<<<4, 1024>>>();
    gn_kernel<<<512, 256>>>(gamma, beta, out);
}